// round 1
// baseline (speedup 1.0000x reference)
#include <cuda_runtime.h>
#include <math.h>
#include <stdint.h>

#define B_ 4
#define T_ 4096
#define D_ 2048
#define H_ 128
#define M_TOT (B_*T_)

// Scratch for Q, K, V projections (device globals: no allocation).
__device__ float g_q[M_TOT * H_];
__device__ float g_k[M_TOT * H_];
__device__ float g_v[M_TOT * H_];

// ---------------------------------------------------------------------------
// Projection GEMM: out[M,H] = x[M,D] @ W[D,H]
// BM=128, BN=128(=H), BK=16, 256 threads, 8x8 register micro-tile.
// blockIdx.y selects Wq / Wk / Wv.
// ---------------------------------------------------------------------------
__global__ __launch_bounds__(256, 2) void proj_kernel(
    const float* __restrict__ x,
    const float* __restrict__ Wq,
    const float* __restrict__ Wk,
    const float* __restrict__ Wv)
{
    const float* W;
    float* out;
    if (blockIdx.y == 0)      { W = Wq; out = g_q; }
    else if (blockIdx.y == 1) { W = Wk; out = g_k; }
    else                      { W = Wv; out = g_v; }

    __shared__ float Xs[16][132];   // transposed: Xs[k][m], stride 132 (16B-aligned rows)
    __shared__ float Ws[16][128];   // Ws[k][n]

    const int tid = threadIdx.x;
    const int tr  = tid >> 4;     // 0..15
    const int tc  = tid & 15;     // 0..15
    const int row0 = blockIdx.x * 128;

    float acc[8][8];
#pragma unroll
    for (int i = 0; i < 8; i++)
#pragma unroll
        for (int j = 0; j < 8; j++) acc[i][j] = 0.f;

    for (int k0 = 0; k0 < D_; k0 += 16) {
        // Load X tile: 128 rows x 16 cols, store transposed.
#pragma unroll
        for (int q = 0; q < 2; q++) {
            int i  = tid * 2 + q;          // 0..511 float4s
            int r  = i >> 2;               // 0..127
            int c4 = (i & 3) * 4;          // 0,4,8,12
            float4 v = *(const float4*)&x[(size_t)(row0 + r) * D_ + k0 + c4];
            Xs[c4 + 0][r] = v.x;
            Xs[c4 + 1][r] = v.y;
            Xs[c4 + 2][r] = v.z;
            Xs[c4 + 3][r] = v.w;
        }
        // Load W tile: 16 rows x 128 cols (coalesced).
#pragma unroll
        for (int q = 0; q < 2; q++) {
            int i  = tid * 2 + q;
            int r  = i >> 5;               // 0..15
            int c4 = (i & 31) * 4;
            *(float4*)&Ws[r][c4] = *(const float4*)&W[(size_t)(k0 + r) * H_ + c4];
        }
        __syncthreads();

#pragma unroll
        for (int k = 0; k < 16; k++) {
            float4 a0 = *(float4*)&Xs[k][tr * 8];
            float4 a1 = *(float4*)&Xs[k][tr * 8 + 4];
            float4 b0 = *(float4*)&Ws[k][tc * 8];
            float4 b1 = *(float4*)&Ws[k][tc * 8 + 4];
            float a[8] = {a0.x, a0.y, a0.z, a0.w, a1.x, a1.y, a1.z, a1.w};
            float b[8] = {b0.x, b0.y, b0.z, b0.w, b1.x, b1.y, b1.z, b1.w};
#pragma unroll
            for (int i = 0; i < 8; i++)
#pragma unroll
                for (int j = 0; j < 8; j++)
                    acc[i][j] += a[i] * b[j];
        }
        __syncthreads();
    }

#pragma unroll
    for (int i = 0; i < 8; i++) {
        size_t r = (size_t)(row0 + tr * 8 + i);
        *(float4*)&out[r * H_ + tc * 8]     = make_float4(acc[i][0], acc[i][1], acc[i][2], acc[i][3]);
        *(float4*)&out[r * H_ + tc * 8 + 4] = make_float4(acc[i][4], acc[i][5], acc[i][6], acc[i][7]);
    }
}

// ---------------------------------------------------------------------------
// Flash attention (causal), fp32.
// Block: 64-query tile for one batch. 256 threads.
// Key loop over 64-key tiles kt = 0..qt.
// Smem strides: Q/K = 129 (avoids 8-way conflicts on 4-row-spaced K reads),
// V = 132 (float4-aligned rows), S = 65 (conflict-free row scans).
// ---------------------------------------------------------------------------
#define QK_PITCH 129
#define V_PITCH  132
#define S_PITCH  65
#define ATTN_SMEM_FLOATS (64*QK_PITCH + 64*QK_PITCH + 64*V_PITCH + 64*S_PITCH + 3*64)
#define ATTN_SMEM_BYTES  (ATTN_SMEM_FLOATS * 4)

__global__ __launch_bounds__(256, 1) void attn_kernel(float* __restrict__ out)
{
    extern __shared__ float sh[];
    float* Qs  = sh;                      // 64 x QK_PITCH
    float* Ks  = Qs + 64 * QK_PITCH;      // 64 x QK_PITCH
    float* Vs  = Ks + 64 * QK_PITCH;      // 64 x V_PITCH (16B-aligned offset)
    float* Ss  = Vs + 64 * V_PITCH;       // 64 x S_PITCH
    float* smM = Ss + 64 * S_PITCH;
    float* smL = smM + 64;
    float* smA = smL + 64;

    const int tid = threadIdx.x;
    const int b   = blockIdx.y;
    const int qt  = (gridDim.x - 1) - blockIdx.x;   // heavy tiles launch first
    const int q0  = qt * 64;

    const int rb  = (tid >> 4) * 4;   // 4-row group: 0,4,...,60
    const int cb4 = (tid & 15) * 4;   // 4-col group: 0,4,...,60

    const float qscale = 0.08838834764831845f;  // 1/sqrt(128)
    const size_t base = (size_t)b * T_ * H_;

    // Load Q tile (pre-scaled).
#pragma unroll
    for (int it = 0; it < 8; it++) {
        int i  = tid + it * 256;       // 0..2047 float4s
        int r  = i >> 5;
        int c4 = (i & 31) * 4;
        float4 v = *(const float4*)&g_q[base + (size_t)(q0 + r) * H_ + c4];
        Qs[r * QK_PITCH + c4 + 0] = v.x * qscale;
        Qs[r * QK_PITCH + c4 + 1] = v.y * qscale;
        Qs[r * QK_PITCH + c4 + 2] = v.z * qscale;
        Qs[r * QK_PITCH + c4 + 3] = v.w * qscale;
    }
    if (tid < 64) {
        smM[tid] = -1e30f;
        smL[tid] = 0.f;
    }

    float O[4][8];
#pragma unroll
    for (int i = 0; i < 4; i++)
#pragma unroll
        for (int j = 0; j < 8; j++) O[i][j] = 0.f;

    const int nkt = qt + 1;
    for (int kt = 0; kt < nkt; kt++) {
        const int k0 = kt * 64;
        __syncthreads();  // previous PV done before overwriting K/V
        // Load K, V tiles.
#pragma unroll
        for (int it = 0; it < 8; it++) {
            int i  = tid + it * 256;
            int r  = i >> 5;
            int c4 = (i & 31) * 4;
            float4 kv = *(const float4*)&g_k[base + (size_t)(k0 + r) * H_ + c4];
            Ks[r * QK_PITCH + c4 + 0] = kv.x;
            Ks[r * QK_PITCH + c4 + 1] = kv.y;
            Ks[r * QK_PITCH + c4 + 2] = kv.z;
            Ks[r * QK_PITCH + c4 + 3] = kv.w;
            float4 vv = *(const float4*)&g_v[base + (size_t)(k0 + r) * H_ + c4];
            *(float4*)&Vs[r * V_PITCH + c4] = vv;
        }
        __syncthreads();

        // S = Q @ K^T  (4x4 micro-tile per thread)
        float accS[4][4];
#pragma unroll
        for (int i = 0; i < 4; i++)
#pragma unroll
            for (int j = 0; j < 4; j++) accS[i][j] = 0.f;

#pragma unroll 4
        for (int h = 0; h < 128; h++) {
            float a[4], bb[4];
#pragma unroll
            for (int i = 0; i < 4; i++) a[i]  = Qs[(rb + i) * QK_PITCH + h];
#pragma unroll
            for (int j = 0; j < 4; j++) bb[j] = Ks[(cb4 + j) * QK_PITCH + h];
#pragma unroll
            for (int i = 0; i < 4; i++)
#pragma unroll
                for (int j = 0; j < 4; j++)
                    accS[i][j] += a[i] * bb[j];
        }

        // Causal mask + store S to smem.
        const bool diag = (kt == qt);
#pragma unroll
        for (int i = 0; i < 4; i++) {
            int qg = q0 + rb + i;
#pragma unroll
            for (int j = 0; j < 4; j++) {
                int kg = k0 + cb4 + j;
                float v = (!diag || kg <= qg) ? accS[i][j] : -1e30f;
                Ss[(rb + i) * S_PITCH + cb4 + j] = v;
            }
        }
        __syncthreads();

        // Online-softmax row stats: one thread per query row.
        if (tid < 64) {
            int r = tid;
            float mold = smM[r];
            float mx = mold;
#pragma unroll 8
            for (int s = 0; s < 64; s++) mx = fmaxf(mx, Ss[r * S_PITCH + s]);
            float alpha = __expf(mold - mx);
            float sum = 0.f;
#pragma unroll 8
            for (int s = 0; s < 64; s++) {
                float p = __expf(Ss[r * S_PITCH + s] - mx);
                Ss[r * S_PITCH + s] = p;
                sum += p;
            }
            smM[r] = mx;
            smL[r] = smL[r] * alpha + sum;
            smA[r] = alpha;
        }
        __syncthreads();

        // Rescale O, then O += P @ V.
        float al[4];
#pragma unroll
        for (int i = 0; i < 4; i++) al[i] = smA[rb + i];
#pragma unroll
        for (int i = 0; i < 4; i++)
#pragma unroll
            for (int j = 0; j < 8; j++) O[i][j] *= al[i];

#pragma unroll 2
        for (int s = 0; s < 64; s++) {
            float p[4];
#pragma unroll
            for (int i = 0; i < 4; i++) p[i] = Ss[(rb + i) * S_PITCH + s];
            float4 v0 = *(float4*)&Vs[s * V_PITCH + cb4];
            float4 v1 = *(float4*)&Vs[s * V_PITCH + 64 + cb4];
#pragma unroll
            for (int i = 0; i < 4; i++) {
                O[i][0] += p[i] * v0.x;
                O[i][1] += p[i] * v0.y;
                O[i][2] += p[i] * v0.z;
                O[i][3] += p[i] * v0.w;
                O[i][4] += p[i] * v1.x;
                O[i][5] += p[i] * v1.y;
                O[i][6] += p[i] * v1.z;
                O[i][7] += p[i] * v1.w;
            }
        }
    }
    __syncthreads();

    // Normalize and write out.
#pragma unroll
    for (int i = 0; i < 4; i++) {
        float inv = 1.f / smL[rb + i];
        size_t row = base + (size_t)(q0 + rb + i) * H_;
        *(float4*)&out[row + cb4]      = make_float4(O[i][0]*inv, O[i][1]*inv, O[i][2]*inv, O[i][3]*inv);
        *(float4*)&out[row + 64 + cb4] = make_float4(O[i][4]*inv, O[i][5]*inv, O[i][6]*inv, O[i][7]*inv);
    }
}

// ---------------------------------------------------------------------------
extern "C" void kernel_launch(void* const* d_in, const int* in_sizes, int n_in,
                              void* d_out, int out_size)
{
    const float* x  = (const float*)d_in[0];
    const float* Wq = (const float*)d_in[1];
    const float* Wk = (const float*)d_in[2];
    const float* Wv = (const float*)d_in[3];
    float* out = (float*)d_out;

    proj_kernel<<<dim3(M_TOT / 128, 3), 256>>>(x, Wq, Wk, Wv);

    cudaFuncSetAttribute(attn_kernel, cudaFuncAttributeMaxDynamicSharedMemorySize,
                         ATTN_SMEM_BYTES);
    attn_kernel<<<dim3(T_ / 64, B_), 256, ATTN_SMEM_BYTES>>>(out);
}

// round 3
// speedup vs baseline: 1.2541x; 1.2541x over previous
#include <cuda_runtime.h>
#include <cuda_bf16.h>
#include <math.h>
#include <stdint.h>

#define B_ 4
#define T_ 4096
#define D_ 2048
#define H_ 128
#define M_TOT (B_*T_)

// ---------------- device scratch (no allocations allowed) -------------------
__device__ float g_q[M_TOT * H_];
__device__ float g_k[M_TOT * H_];
__device__ float g_v[M_TOT * H_];
__device__ __nv_bfloat16 g_xh[(size_t)M_TOT * D_];
__device__ __nv_bfloat16 g_xl[(size_t)M_TOT * D_];
__device__ __nv_bfloat16 g_wh[3 * H_ * D_];   // [tgt][n][k]  (W transposed, K-major)
__device__ __nv_bfloat16 g_wl[3 * H_ * D_];

// ---------------- helpers ---------------------------------------------------
__device__ __forceinline__ uint32_t smem_u32(const void* p) {
    uint32_t a;
    asm("{ .reg .u64 t; cvta.to.shared.u64 t, %1; cvt.u32.u64 %0, t; }" : "=r"(a) : "l"(p));
    return a;
}

#define LDSM_X4(r0, r1, r2, r3, addr) \
    asm volatile("ldmatrix.sync.aligned.m8n8.x4.shared.b16 {%0,%1,%2,%3}, [%4];" \
                 : "=r"(r0), "=r"(r1), "=r"(r2), "=r"(r3) : "r"(addr))

#define MMA16816(d, a, b) \
    asm volatile("mma.sync.aligned.m16n8k16.row.col.f32.bf16.bf16.f32 " \
                 "{%0,%1,%2,%3}, {%4,%5,%6,%7}, {%8,%9}, {%0,%1,%2,%3};" \
                 : "+f"((d)[0]), "+f"((d)[1]), "+f"((d)[2]), "+f"((d)[3]) \
                 : "r"((a)[0]), "r"((a)[1]), "r"((a)[2]), "r"((a)[3]), \
                   "r"((b)[0]), "r"((b)[1]))

// ---------------------------------------------------------------------------
// prep_x: fp32 -> bf16 hi/lo split (x = hi + lo, residual ~2^-18)
// ---------------------------------------------------------------------------
__global__ __launch_bounds__(256) void prep_x(const float* __restrict__ x)
{
    size_t i = (size_t)blockIdx.x * blockDim.x + threadIdx.x;  // float4 index
    float4 v = ((const float4*)x)[i];
    __nv_bfloat16 h0 = __float2bfloat16(v.x);
    __nv_bfloat16 h1 = __float2bfloat16(v.y);
    __nv_bfloat16 h2 = __float2bfloat16(v.z);
    __nv_bfloat16 h3 = __float2bfloat16(v.w);
    __nv_bfloat16 l0 = __float2bfloat16(v.x - __bfloat162float(h0));
    __nv_bfloat16 l1 = __float2bfloat16(v.y - __bfloat162float(h1));
    __nv_bfloat16 l2 = __float2bfloat16(v.z - __bfloat162float(h2));
    __nv_bfloat16 l3 = __float2bfloat16(v.w - __bfloat162float(h3));
    __nv_bfloat162* xh2 = (__nv_bfloat162*)g_xh;
    __nv_bfloat162* xl2 = (__nv_bfloat162*)g_xl;
    xh2[2*i]   = __halves2bfloat162(h0, h1);
    xh2[2*i+1] = __halves2bfloat162(h2, h3);
    xl2[2*i]   = __halves2bfloat162(l0, l1);
    xl2[2*i+1] = __halves2bfloat162(l2, l3);
}

// prep_w: transpose W[D,H] -> [H,D] (K-major) with bf16 hi/lo split
__global__ __launch_bounds__(256) void prep_w(const float* __restrict__ Wq,
                                              const float* __restrict__ Wk,
                                              const float* __restrict__ Wv)
{
    int idx = blockIdx.x * blockDim.x + threadIdx.x;
    if (idx >= 3 * H_ * D_) return;
    int t = idx / (H_ * D_);
    int r = idx % (H_ * D_);
    int n = r / D_;
    int k = r % D_;
    const float* W = (t == 0) ? Wq : (t == 1) ? Wk : Wv;
    float f = W[(size_t)k * H_ + n];
    __nv_bfloat16 h = __float2bfloat16(f);
    g_wh[idx] = h;
    g_wl[idx] = __float2bfloat16(f - __bfloat162float(h));
}

// ---------------------------------------------------------------------------
// proj_mma: out[128-tile, 128] = X[tile, 2048] @ W via mma.sync bf16x3.
// 512 threads = 16 warps (4m x 4n), warp tile 32x32, BK=64.
// Smem pitch 72 bf16 (144B): conflict-free ldmatrix & stores.
// ---------------------------------------------------------------------------
#define PPITCH 72
#define PTILE_ELEMS (128 * PPITCH)
#define PSMEM_BYTES (4 * PTILE_ELEMS * 2)

__global__ __launch_bounds__(512) void proj_mma()
{
    extern __shared__ __nv_bfloat16 sm[];
    __nv_bfloat16* As_h = sm;
    __nv_bfloat16* As_l = sm + PTILE_ELEMS;
    __nv_bfloat16* Bs_h = sm + 2 * PTILE_ELEMS;
    __nv_bfloat16* Bs_l = sm + 3 * PTILE_ELEMS;

    const int tid  = threadIdx.x;
    const int wid  = tid >> 5;
    const int lane = tid & 31;
    const int wm   = wid >> 2;    // 0..3 (m block of 32)
    const int wn   = wid & 3;     // 0..3 (n block of 32)
    const int mt0  = blockIdx.x;
    const int tgt  = blockIdx.y;

    const __nv_bfloat16* Ah = g_xh + (size_t)mt0 * 128 * D_;
    const __nv_bfloat16* Al = g_xl + (size_t)mt0 * 128 * D_;
    const __nv_bfloat16* Bh = g_wh + (size_t)tgt * H_ * D_;
    const __nv_bfloat16* Bl = g_wl + (size_t)tgt * H_ * D_;

    const uint32_t uAh = smem_u32(As_h);
    const uint32_t uAl = smem_u32(As_l);
    const uint32_t uBh = smem_u32(Bs_h);
    const uint32_t uBl = smem_u32(Bs_l);

    // ldmatrix per-lane offsets (bytes)
    const uint32_t a_off = ((uint32_t)(lane & 15) * PPITCH + (lane >> 4) * 8) * 2;
    // A tile rows for this warp: wm*32 + mt*16
    const uint32_t aoff0 = (uint32_t)(wm * 32) * PPITCH * 2 + a_off;
    const uint32_t aoff1 = aoff0 + 16 * PPITCH * 2;
    // B tile rows: wn*32 + bt*16
    const uint32_t boff0 = (uint32_t)(wn * 32) * PPITCH * 2 + a_off;
    const uint32_t boff1 = boff0 + 16 * PPITCH * 2;

    float acc[2][4][4];
#pragma unroll
    for (int i = 0; i < 2; i++)
#pragma unroll
        for (int j = 0; j < 4; j++)
#pragma unroll
            for (int q = 0; q < 4; q++) acc[i][j][q] = 0.f;

    for (int c = 0; c < D_ / 64; c++) {
        const int kc = c * 64;
        __syncthreads();
        // Load 4 tiles: 128 rows x 64 bf16 = 1024 uint4 each; 2 per thread.
#pragma unroll
        for (int q = 0; q < 2; q++) {
            int idx = tid + q * 512;
            int row = idx >> 3;
            int c8  = idx & 7;
            int so  = row * PPITCH + c8 * 8;
            size_t go = (size_t)row * D_ + kc + c8 * 8;
            *(uint4*)&As_h[so] = *(const uint4*)&Ah[go];
            *(uint4*)&As_l[so] = *(const uint4*)&Al[go];
            *(uint4*)&Bs_h[so] = *(const uint4*)&Bh[go];
            *(uint4*)&Bs_l[so] = *(const uint4*)&Bl[go];
        }
        __syncthreads();

#pragma unroll
        for (int ks = 0; ks < 4; ks++) {
            const uint32_t kb = ks * 16 * 2;
            uint32_t ah[2][4], al[2][4], bh[4][2], bl[4][2];
            LDSM_X4(ah[0][0], ah[0][1], ah[0][2], ah[0][3], uAh + aoff0 + kb);
            LDSM_X4(ah[1][0], ah[1][1], ah[1][2], ah[1][3], uAh + aoff1 + kb);
            LDSM_X4(al[0][0], al[0][1], al[0][2], al[0][3], uAl + aoff0 + kb);
            LDSM_X4(al[1][0], al[1][1], al[1][2], al[1][3], uAl + aoff1 + kb);
            uint32_t t0, t1, t2, t3;
            LDSM_X4(t0, t1, t2, t3, uBh + boff0 + kb);
            bh[0][0] = t0; bh[0][1] = t2; bh[1][0] = t1; bh[1][1] = t3;
            LDSM_X4(t0, t1, t2, t3, uBh + boff1 + kb);
            bh[2][0] = t0; bh[2][1] = t2; bh[3][0] = t1; bh[3][1] = t3;
            LDSM_X4(t0, t1, t2, t3, uBl + boff0 + kb);
            bl[0][0] = t0; bl[0][1] = t2; bl[1][0] = t1; bl[1][1] = t3;
            LDSM_X4(t0, t1, t2, t3, uBl + boff1 + kb);
            bl[2][0] = t0; bl[2][1] = t2; bl[3][0] = t1; bl[3][1] = t3;

#pragma unroll
            for (int mi = 0; mi < 2; mi++)
#pragma unroll
                for (int ni = 0; ni < 4; ni++) {
                    MMA16816(acc[mi][ni], ah[mi], bh[ni]);
                    MMA16816(acc[mi][ni], al[mi], bh[ni]);
                    MMA16816(acc[mi][ni], ah[mi], bl[ni]);
                }
        }
    }

    // Epilogue: d frag (m16n8): d0,d1 @ (row=lane/4, col=2*(lane%4)); d2,d3 @ row+8.
    float* out = (tgt == 0) ? g_q : (tgt == 1) ? g_k : g_v;
    const int r0 = mt0 * 128 + wm * 32 + (lane >> 2);
    const int c0 = wn * 32 + (lane & 3) * 2;
#pragma unroll
    for (int mi = 0; mi < 2; mi++)
#pragma unroll
        for (int ni = 0; ni < 4; ni++) {
            int rr = r0 + mi * 16;
            int cc = c0 + ni * 8;
            *(float2*)&out[(size_t)rr * H_ + cc]       = make_float2(acc[mi][ni][0], acc[mi][ni][1]);
            *(float2*)&out[(size_t)(rr + 8) * H_ + cc] = make_float2(acc[mi][ni][2], acc[mi][ni][3]);
        }
}

// ---------------------------------------------------------------------------
// Flash attention (causal), fp32 — unchanged from R1 (passing).
// ---------------------------------------------------------------------------
#define QK_PITCH 129
#define V_PITCH  132
#define S_PITCH  65
#define ATTN_SMEM_FLOATS (64*QK_PITCH + 64*QK_PITCH + 64*V_PITCH + 64*S_PITCH + 3*64)
#define ATTN_SMEM_BYTES  (ATTN_SMEM_FLOATS * 4)

__global__ __launch_bounds__(256, 1) void attn_kernel(float* __restrict__ out)
{
    extern __shared__ float sh[];
    float* Qs  = sh;
    float* Ks  = Qs + 64 * QK_PITCH;
    float* Vs  = Ks + 64 * QK_PITCH;
    float* Ss  = Vs + 64 * V_PITCH;
    float* smM = Ss + 64 * S_PITCH;
    float* smL = smM + 64;
    float* smA = smL + 64;

    const int tid = threadIdx.x;
    const int b   = blockIdx.y;
    const int qt  = (gridDim.x - 1) - blockIdx.x;
    const int q0  = qt * 64;

    const int rb  = (tid >> 4) * 4;
    const int cb4 = (tid & 15) * 4;

    const float qscale = 0.08838834764831845f;
    const size_t base = (size_t)b * T_ * H_;

#pragma unroll
    for (int it = 0; it < 8; it++) {
        int i  = tid + it * 256;
        int r  = i >> 5;
        int c4 = (i & 31) * 4;
        float4 v = *(const float4*)&g_q[base + (size_t)(q0 + r) * H_ + c4];
        Qs[r * QK_PITCH + c4 + 0] = v.x * qscale;
        Qs[r * QK_PITCH + c4 + 1] = v.y * qscale;
        Qs[r * QK_PITCH + c4 + 2] = v.z * qscale;
        Qs[r * QK_PITCH + c4 + 3] = v.w * qscale;
    }
    if (tid < 64) {
        smM[tid] = -1e30f;
        smL[tid] = 0.f;
    }

    float O[4][8];
#pragma unroll
    for (int i = 0; i < 4; i++)
#pragma unroll
        for (int j = 0; j < 8; j++) O[i][j] = 0.f;

    const int nkt = qt + 1;
    for (int kt = 0; kt < nkt; kt++) {
        const int k0 = kt * 64;
        __syncthreads();
#pragma unroll
        for (int it = 0; it < 8; it++) {
            int i  = tid + it * 256;
            int r  = i >> 5;
            int c4 = (i & 31) * 4;
            float4 kv = *(const float4*)&g_k[base + (size_t)(k0 + r) * H_ + c4];
            Ks[r * QK_PITCH + c4 + 0] = kv.x;
            Ks[r * QK_PITCH + c4 + 1] = kv.y;
            Ks[r * QK_PITCH + c4 + 2] = kv.z;
            Ks[r * QK_PITCH + c4 + 3] = kv.w;
            float4 vv = *(const float4*)&g_v[base + (size_t)(k0 + r) * H_ + c4];
            *(float4*)&Vs[r * V_PITCH + c4] = vv;
        }
        __syncthreads();

        float accS[4][4];
#pragma unroll
        for (int i = 0; i < 4; i++)
#pragma unroll
            for (int j = 0; j < 4; j++) accS[i][j] = 0.f;

#pragma unroll 4
        for (int h = 0; h < 128; h++) {
            float a[4], bb[4];
#pragma unroll
            for (int i = 0; i < 4; i++) a[i]  = Qs[(rb + i) * QK_PITCH + h];
#pragma unroll
            for (int j = 0; j < 4; j++) bb[j] = Ks[(cb4 + j) * QK_PITCH + h];
#pragma unroll
            for (int i = 0; i < 4; i++)
#pragma unroll
                for (int j = 0; j < 4; j++)
                    accS[i][j] += a[i] * bb[j];
        }

        const bool diag = (kt == qt);
#pragma unroll
        for (int i = 0; i < 4; i++) {
            int qg = q0 + rb + i;
#pragma unroll
            for (int j = 0; j < 4; j++) {
                int kg = k0 + cb4 + j;
                float v = (!diag || kg <= qg) ? accS[i][j] : -1e30f;
                Ss[(rb + i) * S_PITCH + cb4 + j] = v;
            }
        }
        __syncthreads();

        if (tid < 64) {
            int r = tid;
            float mold = smM[r];
            float mx = mold;
#pragma unroll 8
            for (int s = 0; s < 64; s++) mx = fmaxf(mx, Ss[r * S_PITCH + s]);
            float alpha = __expf(mold - mx);
            float sum = 0.f;
#pragma unroll 8
            for (int s = 0; s < 64; s++) {
                float p = __expf(Ss[r * S_PITCH + s] - mx);
                Ss[r * S_PITCH + s] = p;
                sum += p;
            }
            smM[r] = mx;
            smL[r] = smL[r] * alpha + sum;
            smA[r] = alpha;
        }
        __syncthreads();

        float al[4];
#pragma unroll
        for (int i = 0; i < 4; i++) al[i] = smA[rb + i];
#pragma unroll
        for (int i = 0; i < 4; i++)
#pragma unroll
            for (int j = 0; j < 8; j++) O[i][j] *= al[i];

#pragma unroll 2
        for (int s = 0; s < 64; s++) {
            float p[4];
#pragma unroll
            for (int i = 0; i < 4; i++) p[i] = Ss[(rb + i) * S_PITCH + s];
            float4 v0 = *(float4*)&Vs[s * V_PITCH + cb4];
            float4 v1 = *(float4*)&Vs[s * V_PITCH + 64 + cb4];
#pragma unroll
            for (int i = 0; i < 4; i++) {
                O[i][0] += p[i] * v0.x;
                O[i][1] += p[i] * v0.y;
                O[i][2] += p[i] * v0.z;
                O[i][3] += p[i] * v0.w;
                O[i][4] += p[i] * v1.x;
                O[i][5] += p[i] * v1.y;
                O[i][6] += p[i] * v1.z;
                O[i][7] += p[i] * v1.w;
            }
        }
    }
    __syncthreads();

#pragma unroll
    for (int i = 0; i < 4; i++) {
        float inv = 1.f / smL[rb + i];
        size_t row = base + (size_t)(q0 + rb + i) * H_;
        *(float4*)&out[row + cb4]      = make_float4(O[i][0]*inv, O[i][1]*inv, O[i][2]*inv, O[i][3]*inv);
        *(float4*)&out[row + 64 + cb4] = make_float4(O[i][4]*inv, O[i][5]*inv, O[i][6]*inv, O[i][7]*inv);
    }
}

// ---------------------------------------------------------------------------
extern "C" void kernel_launch(void* const* d_in, const int* in_sizes, int n_in,
                              void* d_out, int out_size)
{
    const float* x  = (const float*)d_in[0];
    const float* Wq = (const float*)d_in[1];
    const float* Wk = (const float*)d_in[2];
    const float* Wv = (const float*)d_in[3];
    float* out = (float*)d_out;

    prep_x<<<(M_TOT * D_ / 4 + 255) / 256, 256>>>(x);
    prep_w<<<(3 * H_ * D_ + 255) / 256, 256>>>(Wq, Wk, Wv);

    cudaFuncSetAttribute(proj_mma, cudaFuncAttributeMaxDynamicSharedMemorySize,
                         PSMEM_BYTES);
    proj_mma<<<dim3(M_TOT / 128, 3), 512, PSMEM_BYTES>>>();

    cudaFuncSetAttribute(attn_kernel, cudaFuncAttributeMaxDynamicSharedMemorySize,
                         ATTN_SMEM_BYTES);
    attn_kernel<<<dim3(T_ / 64, B_), 256, ATTN_SMEM_BYTES>>>(out);
}

// round 5
// speedup vs baseline: 1.5531x; 1.2384x over previous
#include <cuda_runtime.h>
#include <cuda_bf16.h>
#include <math.h>
#include <stdint.h>

#define B_ 4
#define T_ 4096
#define D_ 2048
#define H_ 128
#define M_TOT (B_*T_)

// ---------------- device scratch (no allocations allowed) -------------------
__device__ __nv_bfloat16 g_xh[(size_t)M_TOT * D_];
__device__ __nv_bfloat16 g_xl[(size_t)M_TOT * D_];
__device__ __nv_bfloat16 g_wh[3 * H_ * D_];   // [tgt][n][k]  (W transposed, K-major)
__device__ __nv_bfloat16 g_wl[3 * H_ * D_];
// Projection outputs as bf16 hi/lo (Q pre-scaled by 1/sqrt(H))
__device__ __nv_bfloat16 g_qh[M_TOT * H_];
__device__ __nv_bfloat16 g_ql[M_TOT * H_];
__device__ __nv_bfloat16 g_kh[M_TOT * H_];
__device__ __nv_bfloat16 g_kl[M_TOT * H_];
__device__ __nv_bfloat16 g_vh[M_TOT * H_];
__device__ __nv_bfloat16 g_vl[M_TOT * H_];

// ---------------- helpers ---------------------------------------------------
__device__ __forceinline__ uint32_t smem_u32(const void* p) {
    uint32_t a;
    asm("{ .reg .u64 t; cvta.to.shared.u64 t, %1; cvt.u32.u64 %0, t; }" : "=r"(a) : "l"(p));
    return a;
}

#define LDSM_X4(r0, r1, r2, r3, addr) \
    asm volatile("ldmatrix.sync.aligned.m8n8.x4.shared.b16 {%0,%1,%2,%3}, [%4];" \
                 : "=r"(r0), "=r"(r1), "=r"(r2), "=r"(r3) : "r"(addr))

#define LDSM_X4_T(r0, r1, r2, r3, addr) \
    asm volatile("ldmatrix.sync.aligned.m8n8.x4.trans.shared.b16 {%0,%1,%2,%3}, [%4];" \
                 : "=r"(r0), "=r"(r1), "=r"(r2), "=r"(r3) : "r"(addr))

#define MMA16816(d, a, b) \
    asm volatile("mma.sync.aligned.m16n8k16.row.col.f32.bf16.bf16.f32 " \
                 "{%0,%1,%2,%3}, {%4,%5,%6,%7}, {%8,%9}, {%0,%1,%2,%3};" \
                 : "+f"((d)[0]), "+f"((d)[1]), "+f"((d)[2]), "+f"((d)[3]) \
                 : "r"((a)[0]), "r"((a)[1]), "r"((a)[2]), "r"((a)[3]), \
                   "r"((b)[0]), "r"((b)[1]))

// ---------------------------------------------------------------------------
// prep_x: fp32 -> bf16 hi/lo split (x = hi + lo, residual ~2^-18)
// ---------------------------------------------------------------------------
__global__ __launch_bounds__(256) void prep_x(const float* __restrict__ x)
{
    size_t i = (size_t)blockIdx.x * blockDim.x + threadIdx.x;  // float4 index
    float4 v = ((const float4*)x)[i];
    __nv_bfloat16 h0 = __float2bfloat16(v.x);
    __nv_bfloat16 h1 = __float2bfloat16(v.y);
    __nv_bfloat16 h2 = __float2bfloat16(v.z);
    __nv_bfloat16 h3 = __float2bfloat16(v.w);
    __nv_bfloat16 l0 = __float2bfloat16(v.x - __bfloat162float(h0));
    __nv_bfloat16 l1 = __float2bfloat16(v.y - __bfloat162float(h1));
    __nv_bfloat16 l2 = __float2bfloat16(v.z - __bfloat162float(h2));
    __nv_bfloat16 l3 = __float2bfloat16(v.w - __bfloat162float(h3));
    __nv_bfloat162* xh2 = (__nv_bfloat162*)g_xh;
    __nv_bfloat162* xl2 = (__nv_bfloat162*)g_xl;
    xh2[2*i]   = __halves2bfloat162(h0, h1);
    xh2[2*i+1] = __halves2bfloat162(h2, h3);
    xl2[2*i]   = __halves2bfloat162(l0, l1);
    xl2[2*i+1] = __halves2bfloat162(l2, l3);
}

// prep_w: transpose W[D,H] -> [H,D] (K-major) with bf16 hi/lo split
__global__ __launch_bounds__(256) void prep_w(const float* __restrict__ Wq,
                                              const float* __restrict__ Wk,
                                              const float* __restrict__ Wv)
{
    int idx = blockIdx.x * blockDim.x + threadIdx.x;
    if (idx >= 3 * H_ * D_) return;
    int t = idx / (H_ * D_);
    int r = idx % (H_ * D_);
    int n = r / D_;
    int k = r % D_;
    const float* W = (t == 0) ? Wq : (t == 1) ? Wk : Wv;
    float f = W[(size_t)k * H_ + n];
    __nv_bfloat16 h = __float2bfloat16(f);
    g_wh[idx] = h;
    g_wl[idx] = __float2bfloat16(f - __bfloat162float(h));
}

// ---------------------------------------------------------------------------
// proj_mma: [128-tile, 128] = X[tile, 2048] @ W via mma.sync bf16x3.
// Epilogue writes bf16 hi/lo (Q pre-scaled).
// ---------------------------------------------------------------------------
#define PPR 72
#define PTILE_ELEMS (128 * PPR)
#define PSMEM_BYTES (4 * PTILE_ELEMS * 2)

extern __shared__ char dyn_sm[];

__global__ __launch_bounds__(512) void proj_mma()
{
    __nv_bfloat16* smb = (__nv_bfloat16*)dyn_sm;
    __nv_bfloat16* As_h = smb;
    __nv_bfloat16* As_l = smb + PTILE_ELEMS;
    __nv_bfloat16* Bs_h = smb + 2 * PTILE_ELEMS;
    __nv_bfloat16* Bs_l = smb + 3 * PTILE_ELEMS;

    const int tid  = threadIdx.x;
    const int wid  = tid >> 5;
    const int lane = tid & 31;
    const int wm   = wid >> 2;
    const int wn   = wid & 3;
    const int mt0  = blockIdx.x;
    const int tgt  = blockIdx.y;

    const __nv_bfloat16* Ah = g_xh + (size_t)mt0 * 128 * D_;
    const __nv_bfloat16* Al = g_xl + (size_t)mt0 * 128 * D_;
    const __nv_bfloat16* Bh = g_wh + (size_t)tgt * H_ * D_;
    const __nv_bfloat16* Bl = g_wl + (size_t)tgt * H_ * D_;

    const uint32_t uAh = smem_u32(As_h);
    const uint32_t uAl = smem_u32(As_l);
    const uint32_t uBh = smem_u32(Bs_h);
    const uint32_t uBl = smem_u32(Bs_l);

    const uint32_t a_off = ((uint32_t)(lane & 15) * PPR + (lane >> 4) * 8) * 2;
    const uint32_t aoff0 = (uint32_t)(wm * 32) * PPR * 2 + a_off;
    const uint32_t aoff1 = aoff0 + 16 * PPR * 2;
    const uint32_t boff0 = (uint32_t)(wn * 32) * PPR * 2 + a_off;
    const uint32_t boff1 = boff0 + 16 * PPR * 2;

    float acc[2][4][4];
#pragma unroll
    for (int i = 0; i < 2; i++)
#pragma unroll
        for (int j = 0; j < 4; j++)
#pragma unroll
            for (int q = 0; q < 4; q++) acc[i][j][q] = 0.f;

    for (int c = 0; c < D_ / 64; c++) {
        const int kc = c * 64;
        __syncthreads();
#pragma unroll
        for (int q = 0; q < 2; q++) {
            int idx = tid + q * 512;
            int row = idx >> 3;
            int c8  = idx & 7;
            int so  = row * PPR + c8 * 8;
            size_t go = (size_t)row * D_ + kc + c8 * 8;
            *(uint4*)&As_h[so] = *(const uint4*)&Ah[go];
            *(uint4*)&As_l[so] = *(const uint4*)&Al[go];
            *(uint4*)&Bs_h[so] = *(const uint4*)&Bh[go];
            *(uint4*)&Bs_l[so] = *(const uint4*)&Bl[go];
        }
        __syncthreads();

#pragma unroll
        for (int ks = 0; ks < 4; ks++) {
            const uint32_t kb = ks * 16 * 2;
            uint32_t ah[2][4], al[2][4], bh[4][2], bl[4][2];
            LDSM_X4(ah[0][0], ah[0][1], ah[0][2], ah[0][3], uAh + aoff0 + kb);
            LDSM_X4(ah[1][0], ah[1][1], ah[1][2], ah[1][3], uAh + aoff1 + kb);
            LDSM_X4(al[0][0], al[0][1], al[0][2], al[0][3], uAl + aoff0 + kb);
            LDSM_X4(al[1][0], al[1][1], al[1][2], al[1][3], uAl + aoff1 + kb);
            uint32_t t0, t1, t2, t3;
            LDSM_X4(t0, t1, t2, t3, uBh + boff0 + kb);
            bh[0][0] = t0; bh[0][1] = t2; bh[1][0] = t1; bh[1][1] = t3;
            LDSM_X4(t0, t1, t2, t3, uBh + boff1 + kb);
            bh[2][0] = t0; bh[2][1] = t2; bh[3][0] = t1; bh[3][1] = t3;
            LDSM_X4(t0, t1, t2, t3, uBl + boff0 + kb);
            bl[0][0] = t0; bl[0][1] = t2; bl[1][0] = t1; bl[1][1] = t3;
            LDSM_X4(t0, t1, t2, t3, uBl + boff1 + kb);
            bl[2][0] = t0; bl[2][1] = t2; bl[3][0] = t1; bl[3][1] = t3;

#pragma unroll
            for (int mi = 0; mi < 2; mi++)
#pragma unroll
                for (int ni = 0; ni < 4; ni++) {
                    MMA16816(acc[mi][ni], ah[mi], bh[ni]);
                    MMA16816(acc[mi][ni], al[mi], bh[ni]);
                    MMA16816(acc[mi][ni], ah[mi], bl[ni]);
                }
        }
    }

    // Epilogue: split to bf16 hi/lo; Q pre-scaled by 1/sqrt(H).
    __nv_bfloat16 *oh, *ol;
    if (tgt == 0)      { oh = g_qh; ol = g_ql; }
    else if (tgt == 1) { oh = g_kh; ol = g_kl; }
    else               { oh = g_vh; ol = g_vl; }
    const float scale = (tgt == 0) ? 0.08838834764831845f : 1.0f;

    const int r0 = mt0 * 128 + wm * 32 + (lane >> 2);
    const int c0 = wn * 32 + (lane & 3) * 2;
#pragma unroll
    for (int mi = 0; mi < 2; mi++)
#pragma unroll
        for (int ni = 0; ni < 4; ni++) {
            int cc = c0 + ni * 8;
#pragma unroll
            for (int hh = 0; hh < 2; hh++) {
                int rr = r0 + mi * 16 + hh * 8;
                float v0 = acc[mi][ni][2*hh + 0] * scale;
                float v1 = acc[mi][ni][2*hh + 1] * scale;
                __nv_bfloat16 h0 = __float2bfloat16(v0);
                __nv_bfloat16 h1 = __float2bfloat16(v1);
                __nv_bfloat16 l0 = __float2bfloat16(v0 - __bfloat162float(h0));
                __nv_bfloat16 l1 = __float2bfloat16(v1 - __bfloat162float(h1));
                *(__nv_bfloat162*)&oh[(size_t)rr * H_ + cc] = __halves2bfloat162(h0, h1);
                *(__nv_bfloat162*)&ol[(size_t)rr * H_ + cc] = __halves2bfloat162(l0, l1);
            }
        }
}

// ---------------------------------------------------------------------------
// attn_mma: causal flash attention on mma.sync bf16x3.
// CTA: 128-query tile, key tiles of 64. 8 warps (4m x 2n).
// ---------------------------------------------------------------------------
#define QP 136
#define KP 136
#define VP 136
#define SP 66
#define PP 72

#define OFF_QH 0
#define OFF_QL (OFF_QH + 128*QP*2)
#define OFF_KH (OFF_QL + 128*QP*2)
#define OFF_KL (OFF_KH + 64*KP*2)
#define OFF_VH (OFF_KL + 64*KP*2)
#define OFF_VL (OFF_VH + 64*VP*2)
#define OFF_SS (OFF_VL + 64*VP*2)
#define OFF_PH (OFF_SS + 128*SP*4)
#define OFF_PL (OFF_PH + 128*PP*2)
#define OFF_M  (OFF_PL + 128*PP*2)
#define OFF_L  (OFF_M + 512)
#define OFF_A  (OFF_L + 512)
#define ATTN_SMEM (OFF_A + 512)

__global__ __launch_bounds__(256, 1) void attn_mma(float* __restrict__ out)
{
    char* smc = dyn_sm;
    const uint32_t sb = smem_u32(smc);
    const int tid  = threadIdx.x;
    const int wid  = tid >> 5;
    const int lane = tid & 31;
    const int wm   = wid >> 1;     // 0..3 (32 query rows each)
    const int wn   = wid & 1;      // 0..1
    const int b    = blockIdx.y;
    const int qt   = (gridDim.x - 1) - blockIdx.x;  // heavy first
    const int q0   = qt * 128;
    const size_t gbase = (size_t)b * T_ * H_;

    float* Ss = (float*)(smc + OFF_SS);
    float* fM = (float*)(smc + OFF_M);
    float* fL = (float*)(smc + OFF_L);
    float* fA = (float*)(smc + OFF_A);
    __nv_bfloat16* Ph = (__nv_bfloat16*)(smc + OFF_PH);
    __nv_bfloat16* Pl = (__nv_bfloat16*)(smc + OFF_PL);

    // Load Q tile (128 x 128 bf16, hi+lo).
    {
        const size_t g0 = gbase + (size_t)q0 * H_;
#pragma unroll
        for (int it = 0; it < 8; it++) {
            int idx = tid + it * 256;     // 0..2047 uint4
            int row = idx >> 4;
            int c8  = idx & 15;
            size_t g = g0 + (size_t)row * H_ + c8 * 8;
            int so = (row * QP + c8 * 8) * 2;
            *(uint4*)(smc + OFF_QH + so) = *(const uint4*)&g_qh[g];
            *(uint4*)(smc + OFF_QL + so) = *(const uint4*)&g_ql[g];
        }
    }
    if (tid < 128) { fM[tid] = -1e30f; fL[tid] = 0.f; }

    float O[2][8][4];
#pragma unroll
    for (int mi = 0; mi < 2; mi++)
#pragma unroll
        for (int n = 0; n < 8; n++)
#pragma unroll
            for (int q = 0; q < 4; q++) O[mi][n][q] = 0.f;

    const uint32_t lrow  = (lane & 15);
    const uint32_t lcol8 = (lane >> 4) * 8;
    const int r0 = wm * 32 + (lane >> 2);
    const int c0 = wn * 32 + (lane & 3) * 2;

    const int nkt = 2 * qt + 2;
    for (int kt = 0; kt < nkt; kt++) {
        const int k0 = kt * 64;
        __syncthreads();
        // Load K/V tiles (64 x 128 bf16, hi+lo each).
#pragma unroll
        for (int it = 0; it < 4; it++) {
            int idx = tid + it * 256;     // 0..1023
            int row = idx >> 4;
            int c8  = idx & 15;
            size_t g = gbase + (size_t)(k0 + row) * H_ + c8 * 8;
            int so = (row * KP + c8 * 8) * 2;
            *(uint4*)(smc + OFF_KH + so) = *(const uint4*)&g_kh[g];
            *(uint4*)(smc + OFF_KL + so) = *(const uint4*)&g_kl[g];
            *(uint4*)(smc + OFF_VH + so) = *(const uint4*)&g_vh[g];
            *(uint4*)(smc + OFF_VL + so) = *(const uint4*)&g_vl[g];
        }
        __syncthreads();

        // ---- S = Q @ K^T (M=128, N=64, K=128) ----
        float accS[2][4][4];
#pragma unroll
        for (int mi = 0; mi < 2; mi++)
#pragma unroll
            for (int ni = 0; ni < 4; ni++)
#pragma unroll
                for (int q = 0; q < 4; q++) accS[mi][ni][q] = 0.f;

#pragma unroll
        for (int ks = 0; ks < 8; ks++) {
            uint32_t ah[2][4], al[2][4], bh[4][2], bl[4][2];
            uint32_t aA = sb + OFF_QH + (((wm * 32 + lrow) * QP) + lcol8 + ks * 16) * 2;
            uint32_t aAl = aA + (OFF_QL - OFF_QH);
            LDSM_X4(ah[0][0], ah[0][1], ah[0][2], ah[0][3], aA);
            LDSM_X4(ah[1][0], ah[1][1], ah[1][2], ah[1][3], aA + 16 * QP * 2);
            LDSM_X4(al[0][0], al[0][1], al[0][2], al[0][3], aAl);
            LDSM_X4(al[1][0], al[1][1], al[1][2], al[1][3], aAl + 16 * QP * 2);
            uint32_t bA = sb + OFF_KH + (((wn * 32 + lrow) * KP) + lcol8 + ks * 16) * 2;
            uint32_t bAl = bA + (OFF_KL - OFF_KH);
            uint32_t t0, t1, t2, t3;
            LDSM_X4(t0, t1, t2, t3, bA);
            bh[0][0] = t0; bh[0][1] = t2; bh[1][0] = t1; bh[1][1] = t3;
            LDSM_X4(t0, t1, t2, t3, bA + 16 * KP * 2);
            bh[2][0] = t0; bh[2][1] = t2; bh[3][0] = t1; bh[3][1] = t3;
            LDSM_X4(t0, t1, t2, t3, bAl);
            bl[0][0] = t0; bl[0][1] = t2; bl[1][0] = t1; bl[1][1] = t3;
            LDSM_X4(t0, t1, t2, t3, bAl + 16 * KP * 2);
            bl[2][0] = t0; bl[2][1] = t2; bl[3][0] = t1; bl[3][1] = t3;

#pragma unroll
            for (int mi = 0; mi < 2; mi++)
#pragma unroll
                for (int ni = 0; ni < 4; ni++) {
                    MMA16816(accS[mi][ni], ah[mi], bh[ni]);
                    MMA16816(accS[mi][ni], al[mi], bh[ni]);
                    MMA16816(accS[mi][ni], ah[mi], bl[ni]);
                }
        }

        // Causal mask + store S frags to smem (fp32).
        const bool need_mask = (k0 + 63 > q0);
#pragma unroll
        for (int mi = 0; mi < 2; mi++)
#pragma unroll
            for (int ni = 0; ni < 4; ni++) {
                int rr = r0 + mi * 16;
                int cc = c0 + ni * 8;
                float s00 = accS[mi][ni][0], s01 = accS[mi][ni][1];
                float s10 = accS[mi][ni][2], s11 = accS[mi][ni][3];
                if (need_mask) {
                    int qg0 = q0 + rr, qg1 = q0 + rr + 8;
                    int kg0 = k0 + cc, kg1 = kg0 + 1;
                    if (kg0 > qg0) s00 = -1e30f;
                    if (kg1 > qg0) s01 = -1e30f;
                    if (kg0 > qg1) s10 = -1e30f;
                    if (kg1 > qg1) s11 = -1e30f;
                }
                *(float2*)&Ss[rr * SP + cc]       = make_float2(s00, s01);
                *(float2*)&Ss[(rr + 8) * SP + cc] = make_float2(s10, s11);
            }
        __syncthreads();

        // ---- Online softmax per row; write P as bf16 hi/lo. ----
        if (tid < 128) {
            const int r = tid;
            float mold = fM[r];
            float mx = mold;
#pragma unroll 8
            for (int s = 0; s < 64; s++) mx = fmaxf(mx, Ss[r * SP + s]);
            float alpha = __expf(mold - mx);
            float sum = 0.f;
#pragma unroll 4
            for (int s = 0; s < 64; s++) {
                float p = __expf(Ss[r * SP + s] - mx);
                sum += p;
                __nv_bfloat16 h = __float2bfloat16(p);
                Ph[r * PP + s] = h;
                Pl[r * PP + s] = __float2bfloat16(p - __bfloat162float(h));
            }
            fM[r] = mx;
            fL[r] = fL[r] * alpha + sum;
            fA[r] = alpha;
        }
        __syncthreads();

        // ---- Rescale O, then O += P @ V (M=128, N=128, K=64). ----
        float alv[2][2];
#pragma unroll
        for (int mi = 0; mi < 2; mi++) {
            alv[mi][0] = fA[r0 + mi * 16];
            alv[mi][1] = fA[r0 + mi * 16 + 8];
        }
#pragma unroll
        for (int mi = 0; mi < 2; mi++)
#pragma unroll
            for (int n = 0; n < 8; n++) {
                O[mi][n][0] *= alv[mi][0];
                O[mi][n][1] *= alv[mi][0];
                O[mi][n][2] *= alv[mi][1];
                O[mi][n][3] *= alv[mi][1];
            }

#pragma unroll
        for (int ks = 0; ks < 4; ks++) {
            uint32_t ph[2][4], pl[2][4], vh[8][2], vl[8][2];
            uint32_t aP = sb + OFF_PH + (((wm * 32 + lrow) * PP) + lcol8 + ks * 16) * 2;
            uint32_t aPl = aP + (OFF_PL - OFF_PH);
            LDSM_X4(ph[0][0], ph[0][1], ph[0][2], ph[0][3], aP);
            LDSM_X4(ph[1][0], ph[1][1], ph[1][2], ph[1][3], aP + 16 * PP * 2);
            LDSM_X4(pl[0][0], pl[0][1], pl[0][2], pl[0][3], aPl);
            LDSM_X4(pl[1][0], pl[1][1], pl[1][2], pl[1][3], aPl + 16 * PP * 2);
#pragma unroll
            for (int nj = 0; nj < 4; nj++) {
                uint32_t aV = sb + OFF_VH +
                    (((ks * 16 + lrow) * VP) + wn * 64 + nj * 16 + lcol8) * 2;
                uint32_t t0, t1, t2, t3;
                LDSM_X4_T(t0, t1, t2, t3, aV);
                vh[2*nj][0] = t0; vh[2*nj][1] = t1;
                vh[2*nj+1][0] = t2; vh[2*nj+1][1] = t3;
                LDSM_X4_T(t0, t1, t2, t3, aV + (OFF_VL - OFF_VH));
                vl[2*nj][0] = t0; vl[2*nj][1] = t1;
                vl[2*nj+1][0] = t2; vl[2*nj+1][1] = t3;
            }
#pragma unroll
            for (int mi = 0; mi < 2; mi++)
#pragma unroll
                for (int n = 0; n < 8; n++) {
                    MMA16816(O[mi][n], ph[mi], vh[n]);
                    MMA16816(O[mi][n], pl[mi], vh[n]);
                    MMA16816(O[mi][n], ph[mi], vl[n]);
                }
        }
    }

    // ---- Normalize and write out (fp32). ----
    float il[2][2];
#pragma unroll
    for (int mi = 0; mi < 2; mi++) {
        il[mi][0] = 1.f / fL[r0 + mi * 16];
        il[mi][1] = 1.f / fL[r0 + mi * 16 + 8];
    }
#pragma unroll
    for (int mi = 0; mi < 2; mi++)
#pragma unroll
        for (int n = 0; n < 8; n++) {
            int row = q0 + r0 + mi * 16;
            int col = wn * 64 + n * 8 + (lane & 3) * 2;
            *(float2*)&out[gbase + (size_t)row * H_ + col] =
                make_float2(O[mi][n][0] * il[mi][0], O[mi][n][1] * il[mi][0]);
            *(float2*)&out[gbase + (size_t)(row + 8) * H_ + col] =
                make_float2(O[mi][n][2] * il[mi][1], O[mi][n][3] * il[mi][1]);
        }
}

// ---------------------------------------------------------------------------
extern "C" void kernel_launch(void* const* d_in, const int* in_sizes, int n_in,
                              void* d_out, int out_size)
{
    const float* x  = (const float*)d_in[0];
    const float* Wq = (const float*)d_in[1];
    const float* Wk = (const float*)d_in[2];
    const float* Wv = (const float*)d_in[3];
    float* out = (float*)d_out;

    prep_x<<<(M_TOT * D_ / 4 + 255) / 256, 256>>>(x);
    prep_w<<<(3 * H_ * D_ + 255) / 256, 256>>>(Wq, Wk, Wv);

    cudaFuncSetAttribute(proj_mma, cudaFuncAttributeMaxDynamicSharedMemorySize,
                         PSMEM_BYTES);
    proj_mma<<<dim3(M_TOT / 128, 3), 512, PSMEM_BYTES>>>();

    cudaFuncSetAttribute(attn_mma, cudaFuncAttributeMaxDynamicSharedMemorySize,
                         ATTN_SMEM);
    attn_mma<<<dim3(T_ / 128, B_), 256, ATTN_SMEM>>>(out);
}

// round 6
// speedup vs baseline: 2.3072x; 1.4856x over previous
#include <cuda_runtime.h>
#include <cuda_bf16.h>
#include <math.h>
#include <stdint.h>

#define B_ 4
#define T_ 4096
#define D_ 2048
#define H_ 128
#define M_TOT (B_*T_)

// ---------------- device scratch (no allocations allowed) -------------------
__device__ __nv_bfloat16 g_xh[(size_t)M_TOT * D_];
__device__ __nv_bfloat16 g_xl[(size_t)M_TOT * D_];
__device__ __nv_bfloat16 g_wh[3 * H_ * D_];   // [tgt][n][k]  (W transposed, K-major)
__device__ __nv_bfloat16 g_wl[3 * H_ * D_];
// Projection outputs as bf16 hi/lo (Q pre-scaled by 1/sqrt(H))
__device__ __nv_bfloat16 g_qh[M_TOT * H_];
__device__ __nv_bfloat16 g_ql[M_TOT * H_];
__device__ __nv_bfloat16 g_kh[M_TOT * H_];
__device__ __nv_bfloat16 g_kl[M_TOT * H_];
__device__ __nv_bfloat16 g_vh[M_TOT * H_];
__device__ __nv_bfloat16 g_vl[M_TOT * H_];

// ---------------- helpers ---------------------------------------------------
__device__ __forceinline__ uint32_t smem_u32(const void* p) {
    uint32_t a;
    asm("{ .reg .u64 t; cvta.to.shared.u64 t, %1; cvt.u32.u64 %0, t; }" : "=r"(a) : "l"(p));
    return a;
}

#define LDSM_X4(r0, r1, r2, r3, addr) \
    asm volatile("ldmatrix.sync.aligned.m8n8.x4.shared.b16 {%0,%1,%2,%3}, [%4];" \
                 : "=r"(r0), "=r"(r1), "=r"(r2), "=r"(r3) : "r"(addr))

#define LDSM_X4_T(r0, r1, r2, r3, addr) \
    asm volatile("ldmatrix.sync.aligned.m8n8.x4.trans.shared.b16 {%0,%1,%2,%3}, [%4];" \
                 : "=r"(r0), "=r"(r1), "=r"(r2), "=r"(r3) : "r"(addr))

#define MMA16816(d, a, b) \
    asm volatile("mma.sync.aligned.m16n8k16.row.col.f32.bf16.bf16.f32 " \
                 "{%0,%1,%2,%3}, {%4,%5,%6,%7}, {%8,%9}, {%0,%1,%2,%3};" \
                 : "+f"((d)[0]), "+f"((d)[1]), "+f"((d)[2]), "+f"((d)[3]) \
                 : "r"((a)[0]), "r"((a)[1]), "r"((a)[2]), "r"((a)[3]), \
                   "r"((b)[0]), "r"((b)[1]))

#define CP_ASYNC16(s, g) \
    asm volatile("cp.async.cg.shared.global [%0], [%1], 16;" :: "r"(s), "l"(g))
#define CP_COMMIT() asm volatile("cp.async.commit_group;" ::: "memory")
#define CP_WAIT0()  asm volatile("cp.async.wait_group 0;" ::: "memory")

__device__ __forceinline__ uint32_t pack_bf16(float a, float b) {
    __nv_bfloat162 t = __halves2bfloat162(__float2bfloat16(a), __float2bfloat16(b));
    return *(uint32_t*)&t;
}

// ---------------------------------------------------------------------------
// prep_x: fp32 -> bf16 hi/lo split (x = hi + lo, residual ~2^-18)
// ---------------------------------------------------------------------------
__global__ __launch_bounds__(256) void prep_x(const float* __restrict__ x)
{
    size_t i = (size_t)blockIdx.x * blockDim.x + threadIdx.x;
    float4 v = ((const float4*)x)[i];
    __nv_bfloat16 h0 = __float2bfloat16(v.x);
    __nv_bfloat16 h1 = __float2bfloat16(v.y);
    __nv_bfloat16 h2 = __float2bfloat16(v.z);
    __nv_bfloat16 h3 = __float2bfloat16(v.w);
    __nv_bfloat16 l0 = __float2bfloat16(v.x - __bfloat162float(h0));
    __nv_bfloat16 l1 = __float2bfloat16(v.y - __bfloat162float(h1));
    __nv_bfloat16 l2 = __float2bfloat16(v.z - __bfloat162float(h2));
    __nv_bfloat16 l3 = __float2bfloat16(v.w - __bfloat162float(h3));
    __nv_bfloat162* xh2 = (__nv_bfloat162*)g_xh;
    __nv_bfloat162* xl2 = (__nv_bfloat162*)g_xl;
    xh2[2*i]   = __halves2bfloat162(h0, h1);
    xh2[2*i+1] = __halves2bfloat162(h2, h3);
    xl2[2*i]   = __halves2bfloat162(l0, l1);
    xl2[2*i+1] = __halves2bfloat162(l2, l3);
}

// prep_w: transpose W[D,H] -> [H,D] (K-major) with bf16 hi/lo split
__global__ __launch_bounds__(256) void prep_w(const float* __restrict__ Wq,
                                              const float* __restrict__ Wk,
                                              const float* __restrict__ Wv)
{
    int idx = blockIdx.x * blockDim.x + threadIdx.x;
    if (idx >= 3 * H_ * D_) return;
    int t = idx / (H_ * D_);
    int r = idx % (H_ * D_);
    int n = r / D_;
    int k = r % D_;
    const float* W = (t == 0) ? Wq : (t == 1) ? Wk : Wv;
    float f = W[(size_t)k * H_ + n];
    __nv_bfloat16 h = __float2bfloat16(f);
    g_wh[idx] = h;
    g_wl[idx] = __float2bfloat16(f - __bfloat162float(h));
}

// ---------------------------------------------------------------------------
// proj_mma: [128-tile, 128] = X[tile, 2048] @ W via mma.sync bf16x3. (R5-proven)
// ---------------------------------------------------------------------------
#define PPR 72
#define PTILE_ELEMS (128 * PPR)
#define PSMEM_BYTES (4 * PTILE_ELEMS * 2)

extern __shared__ char dyn_sm[];

__global__ __launch_bounds__(512) void proj_mma()
{
    __nv_bfloat16* smb = (__nv_bfloat16*)dyn_sm;
    __nv_bfloat16* As_h = smb;
    __nv_bfloat16* As_l = smb + PTILE_ELEMS;
    __nv_bfloat16* Bs_h = smb + 2 * PTILE_ELEMS;
    __nv_bfloat16* Bs_l = smb + 3 * PTILE_ELEMS;

    const int tid  = threadIdx.x;
    const int wid  = tid >> 5;
    const int lane = tid & 31;
    const int wm   = wid >> 2;
    const int wn   = wid & 3;
    const int mt0  = blockIdx.x;
    const int tgt  = blockIdx.y;

    const __nv_bfloat16* Ah = g_xh + (size_t)mt0 * 128 * D_;
    const __nv_bfloat16* Al = g_xl + (size_t)mt0 * 128 * D_;
    const __nv_bfloat16* Bh = g_wh + (size_t)tgt * H_ * D_;
    const __nv_bfloat16* Bl = g_wl + (size_t)tgt * H_ * D_;

    const uint32_t uAh = smem_u32(As_h);
    const uint32_t uAl = smem_u32(As_l);
    const uint32_t uBh = smem_u32(Bs_h);
    const uint32_t uBl = smem_u32(Bs_l);

    const uint32_t a_off = ((uint32_t)(lane & 15) * PPR + (lane >> 4) * 8) * 2;
    const uint32_t aoff0 = (uint32_t)(wm * 32) * PPR * 2 + a_off;
    const uint32_t aoff1 = aoff0 + 16 * PPR * 2;
    const uint32_t boff0 = (uint32_t)(wn * 32) * PPR * 2 + a_off;
    const uint32_t boff1 = boff0 + 16 * PPR * 2;

    float acc[2][4][4];
#pragma unroll
    for (int i = 0; i < 2; i++)
#pragma unroll
        for (int j = 0; j < 4; j++)
#pragma unroll
            for (int q = 0; q < 4; q++) acc[i][j][q] = 0.f;

    for (int c = 0; c < D_ / 64; c++) {
        const int kc = c * 64;
        __syncthreads();
#pragma unroll
        for (int q = 0; q < 2; q++) {
            int idx = tid + q * 512;
            int row = idx >> 3;
            int c8  = idx & 7;
            int so  = row * PPR + c8 * 8;
            size_t go = (size_t)row * D_ + kc + c8 * 8;
            *(uint4*)&As_h[so] = *(const uint4*)&Ah[go];
            *(uint4*)&As_l[so] = *(const uint4*)&Al[go];
            *(uint4*)&Bs_h[so] = *(const uint4*)&Bh[go];
            *(uint4*)&Bs_l[so] = *(const uint4*)&Bl[go];
        }
        __syncthreads();

#pragma unroll
        for (int ks = 0; ks < 4; ks++) {
            const uint32_t kb = ks * 16 * 2;
            uint32_t ah[2][4], al[2][4], bh[4][2], bl[4][2];
            LDSM_X4(ah[0][0], ah[0][1], ah[0][2], ah[0][3], uAh + aoff0 + kb);
            LDSM_X4(ah[1][0], ah[1][1], ah[1][2], ah[1][3], uAh + aoff1 + kb);
            LDSM_X4(al[0][0], al[0][1], al[0][2], al[0][3], uAl + aoff0 + kb);
            LDSM_X4(al[1][0], al[1][1], al[1][2], al[1][3], uAl + aoff1 + kb);
            uint32_t t0, t1, t2, t3;
            LDSM_X4(t0, t1, t2, t3, uBh + boff0 + kb);
            bh[0][0] = t0; bh[0][1] = t2; bh[1][0] = t1; bh[1][1] = t3;
            LDSM_X4(t0, t1, t2, t3, uBh + boff1 + kb);
            bh[2][0] = t0; bh[2][1] = t2; bh[3][0] = t1; bh[3][1] = t3;
            LDSM_X4(t0, t1, t2, t3, uBl + boff0 + kb);
            bl[0][0] = t0; bl[0][1] = t2; bl[1][0] = t1; bl[1][1] = t3;
            LDSM_X4(t0, t1, t2, t3, uBl + boff1 + kb);
            bl[2][0] = t0; bl[2][1] = t2; bl[3][0] = t1; bl[3][1] = t3;

#pragma unroll
            for (int mi = 0; mi < 2; mi++)
#pragma unroll
                for (int ni = 0; ni < 4; ni++) {
                    MMA16816(acc[mi][ni], ah[mi], bh[ni]);
                    MMA16816(acc[mi][ni], al[mi], bh[ni]);
                    MMA16816(acc[mi][ni], ah[mi], bl[ni]);
                }
        }
    }

    __nv_bfloat16 *oh, *ol;
    if (tgt == 0)      { oh = g_qh; ol = g_ql; }
    else if (tgt == 1) { oh = g_kh; ol = g_kl; }
    else               { oh = g_vh; ol = g_vl; }
    const float scale = (tgt == 0) ? 0.08838834764831845f : 1.0f;

    const int r0 = mt0 * 128 + wm * 32 + (lane >> 2);
    const int c0 = wn * 32 + (lane & 3) * 2;
#pragma unroll
    for (int mi = 0; mi < 2; mi++)
#pragma unroll
        for (int ni = 0; ni < 4; ni++) {
            int cc = c0 + ni * 8;
#pragma unroll
            for (int hh = 0; hh < 2; hh++) {
                int rr = r0 + mi * 16 + hh * 8;
                float v0 = acc[mi][ni][2*hh + 0] * scale;
                float v1 = acc[mi][ni][2*hh + 1] * scale;
                __nv_bfloat16 h0 = __float2bfloat16(v0);
                __nv_bfloat16 h1 = __float2bfloat16(v1);
                __nv_bfloat16 l0 = __float2bfloat16(v0 - __bfloat162float(h0));
                __nv_bfloat16 l1 = __float2bfloat16(v1 - __bfloat162float(h1));
                *(__nv_bfloat162*)&oh[(size_t)rr * H_ + cc] = __halves2bfloat162(h0, h1);
                *(__nv_bfloat162*)&ol[(size_t)rr * H_ + cc] = __halves2bfloat162(l0, l1);
            }
        }
}

// ---------------------------------------------------------------------------
// attn_mma: fragment-resident causal flash attention, bf16x3 mma.sync.
// 8 warps x m16 rows each; softmax in registers; cp.async double-buffered K/V.
// ---------------------------------------------------------------------------
#define QP 136
#define KP 136
#define QARR (128 * QP * 2)          // 34816 bytes per Q array
#define KARR (64 * KP * 2)           // 17408 bytes per K/V array
#define OFF_QH 0
#define OFF_QL QARR
#define OFF_STG (2 * QARR)           // stages start
#define STG_SZ (4 * KARR)            // KH, KL, VH, VL
#define ATTN_SMEM (OFF_STG + 2 * STG_SZ)   // 208896 bytes

__global__ __launch_bounds__(256, 1) void attn_mma(float* __restrict__ out)
{
    char* smc = dyn_sm;
    const uint32_t sb = smem_u32(smc);
    const int tid  = threadIdx.x;
    const int w    = tid >> 5;            // 0..7: rows [16w, 16w+16)
    const int lane = tid & 31;
    const int b    = blockIdx.y;
    const int qt   = (gridDim.x - 1) - blockIdx.x;  // heavy first
    const int q0   = qt * 128;
    const size_t gbase = (size_t)b * T_ * H_;

    const uint32_t lrow  = (lane & 15);
    const uint32_t lcol8 = (lane >> 4) * 8;
    const int rA = (lane >> 2);           // local row in m16 (and rA+8)
    const int cq = (lane & 3) * 2;        // col pair base within n8

    // ---- Load Q tile (plain loads; covered by first sync) ----
    {
        const size_t g0 = gbase + (size_t)q0 * H_;
#pragma unroll
        for (int it = 0; it < 8; it++) {
            int idx = tid + it * 256;     // 0..2047 uint4
            int row = idx >> 4;
            int c8  = idx & 15;
            size_t g = g0 + (size_t)row * H_ + c8 * 8;
            int so = (row * QP + c8 * 8) * 2;
            *(uint4*)(smc + OFF_QH + so) = *(const uint4*)&g_qh[g];
            *(uint4*)(smc + OFF_QL + so) = *(const uint4*)&g_ql[g];
        }
    }

    const int nkt = 2 * qt + 2;

    // ---- cp.async issue helper (inline): tile kt -> stage st ----
    // 4 arrays x 64 rows x 16 8-elt chunks = 4096 chunks; 16 per thread.
    {
        const int kt = 0, st = 0;
        const int k0 = kt * 64;
#pragma unroll
        for (int it = 0; it < 16; it++) {
            int idx = tid + it * 256;
            int arr = idx >> 10;
            int row = (idx >> 4) & 63;
            int c8  = idx & 15;
            const __nv_bfloat16* src =
                (arr == 0) ? g_kh : (arr == 1) ? g_kl : (arr == 2) ? g_vh : g_vl;
            uint32_t s = sb + OFF_STG + st * STG_SZ + arr * KARR + (row * KP + c8 * 8) * 2;
            const __nv_bfloat16* g = src + gbase + (size_t)(k0 + row) * H_ + c8 * 8;
            CP_ASYNC16(s, g);
        }
        CP_COMMIT();
    }

    // ---- Per-thread state ----
    float O[16][4];
#pragma unroll
    for (int n = 0; n < 16; n++)
#pragma unroll
        for (int q = 0; q < 4; q++) O[n][q] = 0.f;
    float mA = -1e30f, mB = -1e30f, lA = 0.f, lB = 0.f;

    for (int kt = 0; kt < nkt; kt++) {
        const int st = kt & 1;
        const uint32_t stK = sb + OFF_STG + st * STG_SZ;
        CP_WAIT0();
        __syncthreads();   // tile kt ready; all warps done with stage st from kt-2

        // Prefetch tile kt+1 into the other stage.
        if (kt + 1 < nkt) {
            const int k0n = (kt + 1) * 64;
            const int stn = (kt + 1) & 1;
#pragma unroll
            for (int it = 0; it < 16; it++) {
                int idx = tid + it * 256;
                int arr = idx >> 10;
                int row = (idx >> 4) & 63;
                int c8  = idx & 15;
                const __nv_bfloat16* src =
                    (arr == 0) ? g_kh : (arr == 1) ? g_kl : (arr == 2) ? g_vh : g_vl;
                uint32_t s = sb + OFF_STG + stn * STG_SZ + arr * KARR + (row * KP + c8 * 8) * 2;
                const __nv_bfloat16* g = src + gbase + (size_t)(k0n + row) * H_ + c8 * 8;
                CP_ASYNC16(s, g);
            }
            CP_COMMIT();
        }

        const int k0 = kt * 64;

        // ---- S = Q K^T : M=16 (this warp), N=64, K=128 ----
        float accS[8][4];
#pragma unroll
        for (int n = 0; n < 8; n++)
#pragma unroll
            for (int q = 0; q < 4; q++) accS[n][q] = 0.f;

#pragma unroll
        for (int ks = 0; ks < 8; ks++) {
            uint32_t ah[4], al[4], bh[8][2], bl[8][2];
            uint32_t aQ = sb + OFF_QH + (((16 * w + lrow) * QP) + lcol8 + ks * 16) * 2;
            LDSM_X4(ah[0], ah[1], ah[2], ah[3], aQ);
            LDSM_X4(al[0], al[1], al[2], al[3], aQ + (OFF_QL - OFF_QH));
            uint32_t t0, t1, t2, t3;
#pragma unroll
            for (int nj = 0; nj < 4; nj++) {
                uint32_t aK = stK + (((nj * 16 + lrow) * KP) + lcol8 + ks * 16) * 2;
                LDSM_X4(t0, t1, t2, t3, aK);
                bh[2*nj][0] = t0; bh[2*nj][1] = t2;
                bh[2*nj+1][0] = t1; bh[2*nj+1][1] = t3;
                LDSM_X4(t0, t1, t2, t3, aK + KARR);
                bl[2*nj][0] = t0; bl[2*nj][1] = t2;
                bl[2*nj+1][0] = t1; bl[2*nj+1][1] = t3;
            }
#pragma unroll
            for (int n = 0; n < 8; n++) {
                MMA16816(accS[n], ah, bh[n]);
                MMA16816(accS[n], al, bh[n]);
                MMA16816(accS[n], ah, bl[n]);
            }
        }

        // ---- Causal mask (in-register) ----
        if (k0 + 63 > q0 + 16 * w) {
            const int qgA = q0 + 16 * w + rA;
            const int qgB = qgA + 8;
#pragma unroll
            for (int n = 0; n < 8; n++) {
                int kg0 = k0 + n * 8 + cq;
                int kg1 = kg0 + 1;
                if (kg0 > qgA) accS[n][0] = -1e30f;
                if (kg1 > qgA) accS[n][1] = -1e30f;
                if (kg0 > qgB) accS[n][2] = -1e30f;
                if (kg1 > qgB) accS[n][3] = -1e30f;
            }
        }

        // ---- Online softmax in registers ----
        float mxA = -1e30f, mxB = -1e30f;
#pragma unroll
        for (int n = 0; n < 8; n++) {
            mxA = fmaxf(mxA, fmaxf(accS[n][0], accS[n][1]));
            mxB = fmaxf(mxB, fmaxf(accS[n][2], accS[n][3]));
        }
        mxA = fmaxf(mxA, __shfl_xor_sync(0xffffffffu, mxA, 1));
        mxA = fmaxf(mxA, __shfl_xor_sync(0xffffffffu, mxA, 2));
        mxB = fmaxf(mxB, __shfl_xor_sync(0xffffffffu, mxB, 1));
        mxB = fmaxf(mxB, __shfl_xor_sync(0xffffffffu, mxB, 2));

        float mAn = fmaxf(mA, mxA);
        float mBn = fmaxf(mB, mxB);
        float aAl = __expf(mA - mAn);
        float aBl = __expf(mB - mBn);
        mA = mAn; mB = mBn;

        float sA = 0.f, sB = 0.f;
#pragma unroll
        for (int n = 0; n < 8; n++) {
            accS[n][0] = __expf(accS[n][0] - mAn);
            accS[n][1] = __expf(accS[n][1] - mAn);
            accS[n][2] = __expf(accS[n][2] - mBn);
            accS[n][3] = __expf(accS[n][3] - mBn);
            sA += accS[n][0] + accS[n][1];
            sB += accS[n][2] + accS[n][3];
        }
        sA += __shfl_xor_sync(0xffffffffu, sA, 1);
        sA += __shfl_xor_sync(0xffffffffu, sA, 2);
        sB += __shfl_xor_sync(0xffffffffu, sB, 1);
        sB += __shfl_xor_sync(0xffffffffu, sB, 2);
        lA = lA * aAl + sA;
        lB = lB * aBl + sB;

        // Rescale O.
#pragma unroll
        for (int n = 0; n < 16; n++) {
            O[n][0] *= aAl; O[n][1] *= aAl;
            O[n][2] *= aBl; O[n][3] *= aBl;
        }

        // ---- O += P V : K=64 (4 k-steps), N=128; P from fragments ----
        const uint32_t stV = stK + 2 * KARR;
#pragma unroll
        for (int ks = 0; ks < 4; ks++) {
            // Pack P hi/lo a-frags from accS frags 2ks, 2ks+1.
            uint32_t ph[4], pl[4];
            {
                const int j0 = 2 * ks, j1 = 2 * ks + 1;
                float p00 = accS[j0][0], p01 = accS[j0][1];
                float p02 = accS[j0][2], p03 = accS[j0][3];
                float p10 = accS[j1][0], p11 = accS[j1][1];
                float p12 = accS[j1][2], p13 = accS[j1][3];
                ph[0] = pack_bf16(p00, p01);
                ph[1] = pack_bf16(p02, p03);
                ph[2] = pack_bf16(p10, p11);
                ph[3] = pack_bf16(p12, p13);
                __nv_bfloat162* h;
                h = (__nv_bfloat162*)&ph[0];
                pl[0] = pack_bf16(p00 - __bfloat162float(h->x), p01 - __bfloat162float(h->y));
                h = (__nv_bfloat162*)&ph[1];
                pl[1] = pack_bf16(p02 - __bfloat162float(h->x), p03 - __bfloat162float(h->y));
                h = (__nv_bfloat162*)&ph[2];
                pl[2] = pack_bf16(p10 - __bfloat162float(h->x), p11 - __bfloat162float(h->y));
                h = (__nv_bfloat162*)&ph[3];
                pl[3] = pack_bf16(p12 - __bfloat162float(h->x), p13 - __bfloat162float(h->y));
            }

            uint32_t vh[16][2], vl[16][2];
            uint32_t t0, t1, t2, t3;
#pragma unroll
            for (int nj = 0; nj < 8; nj++) {
                uint32_t aV = stV + (((ks * 16 + lrow) * KP) + nj * 16 + lcol8) * 2;
                LDSM_X4_T(t0, t1, t2, t3, aV);
                vh[2*nj][0] = t0; vh[2*nj][1] = t1;
                vh[2*nj+1][0] = t2; vh[2*nj+1][1] = t3;
                LDSM_X4_T(t0, t1, t2, t3, aV + KARR);
                vl[2*nj][0] = t0; vl[2*nj][1] = t1;
                vl[2*nj+1][0] = t2; vl[2*nj+1][1] = t3;
            }
#pragma unroll
            for (int n = 0; n < 16; n++) {
                MMA16816(O[n], ph, vh[n]);
                MMA16816(O[n], pl, vh[n]);
                MMA16816(O[n], ph, vl[n]);
            }
        }
    }

    // ---- Normalize and write out ----
    const float ilA = 1.f / lA;
    const float ilB = 1.f / lB;
    const int rowA = q0 + 16 * w + rA;
#pragma unroll
    for (int n = 0; n < 16; n++) {
        int col = n * 8 + cq;
        *(float2*)&out[gbase + (size_t)rowA * H_ + col] =
            make_float2(O[n][0] * ilA, O[n][1] * ilA);
        *(float2*)&out[gbase + (size_t)(rowA + 8) * H_ + col] =
            make_float2(O[n][2] * ilB, O[n][3] * ilB);
    }
}

// ---------------------------------------------------------------------------
extern "C" void kernel_launch(void* const* d_in, const int* in_sizes, int n_in,
                              void* d_out, int out_size)
{
    const float* x  = (const float*)d_in[0];
    const float* Wq = (const float*)d_in[1];
    const float* Wk = (const float*)d_in[2];
    const float* Wv = (const float*)d_in[3];
    float* out = (float*)d_out;

    prep_x<<<(M_TOT * D_ / 4 + 255) / 256, 256>>>(x);
    prep_w<<<(3 * H_ * D_ + 255) / 256, 256>>>(Wq, Wk, Wv);

    cudaFuncSetAttribute(proj_mma, cudaFuncAttributeMaxDynamicSharedMemorySize,
                         PSMEM_BYTES);
    proj_mma<<<dim3(M_TOT / 128, 3), 512, PSMEM_BYTES>>>();

    cudaFuncSetAttribute(attn_mma, cudaFuncAttributeMaxDynamicSharedMemorySize,
                         ATTN_SMEM);
    attn_mma<<<dim3(T_ / 128, B_), 256, ATTN_SMEM>>>(out);
}

// round 7
// speedup vs baseline: 3.3613x; 1.4569x over previous
#include <cuda_runtime.h>
#include <cuda_bf16.h>
#include <math.h>
#include <stdint.h>

#define B_ 4
#define T_ 4096
#define D_ 2048
#define H_ 128
#define M_TOT (B_*T_)

// ---------------- device scratch (no allocations allowed) -------------------
__device__ __nv_bfloat16 g_xh[(size_t)M_TOT * D_];
__device__ __nv_bfloat16 g_xl[(size_t)M_TOT * D_];
__device__ __nv_bfloat16 g_wh[3 * H_ * D_];
__device__ __nv_bfloat16 g_wl[3 * H_ * D_];
__device__ __nv_bfloat16 g_qh[M_TOT * H_];
__device__ __nv_bfloat16 g_ql[M_TOT * H_];
__device__ __nv_bfloat16 g_kh[M_TOT * H_];
__device__ __nv_bfloat16 g_kl[M_TOT * H_];
__device__ __nv_bfloat16 g_vh[M_TOT * H_];
__device__ __nv_bfloat16 g_vl[M_TOT * H_];
// Split-KV partials: [half][row][col] unnormalized O; per-row m, l.
__device__ float g_po[2 * (size_t)M_TOT * H_];
__device__ float g_pm[2 * M_TOT];
__device__ float g_pl[2 * M_TOT];

// ---------------- helpers ---------------------------------------------------
__device__ __forceinline__ uint32_t smem_u32(const void* p) {
    uint32_t a;
    asm("{ .reg .u64 t; cvta.to.shared.u64 t, %1; cvt.u32.u64 %0, t; }" : "=r"(a) : "l"(p));
    return a;
}

#define LDSM_X4(r0, r1, r2, r3, addr) \
    asm volatile("ldmatrix.sync.aligned.m8n8.x4.shared.b16 {%0,%1,%2,%3}, [%4];" \
                 : "=r"(r0), "=r"(r1), "=r"(r2), "=r"(r3) : "r"(addr))

#define LDSM_X4_T(r0, r1, r2, r3, addr) \
    asm volatile("ldmatrix.sync.aligned.m8n8.x4.trans.shared.b16 {%0,%1,%2,%3}, [%4];" \
                 : "=r"(r0), "=r"(r1), "=r"(r2), "=r"(r3) : "r"(addr))

#define MMA16816(d, a, b) \
    asm volatile("mma.sync.aligned.m16n8k16.row.col.f32.bf16.bf16.f32 " \
                 "{%0,%1,%2,%3}, {%4,%5,%6,%7}, {%8,%9}, {%0,%1,%2,%3};" \
                 : "+f"((d)[0]), "+f"((d)[1]), "+f"((d)[2]), "+f"((d)[3]) \
                 : "r"((a)[0]), "r"((a)[1]), "r"((a)[2]), "r"((a)[3]), \
                   "r"((b)[0]), "r"((b)[1]))

#define CP_ASYNC16(s, g) \
    asm volatile("cp.async.cg.shared.global [%0], [%1], 16;" :: "r"(s), "l"(g))
#define CP_COMMIT() asm volatile("cp.async.commit_group;" ::: "memory")
#define CP_WAIT0()  asm volatile("cp.async.wait_group 0;" ::: "memory")

__device__ __forceinline__ uint32_t pack_bf16(float a, float b) {
    __nv_bfloat162 t = __halves2bfloat162(__float2bfloat16(a), __float2bfloat16(b));
    return *(uint32_t*)&t;
}

extern __shared__ char dyn_sm[];

// ---------------------------------------------------------------------------
// prep_x: fp32 -> bf16 hi/lo split
// ---------------------------------------------------------------------------
__global__ __launch_bounds__(256) void prep_x(const float* __restrict__ x)
{
    size_t i = (size_t)blockIdx.x * blockDim.x + threadIdx.x;
    float4 v = ((const float4*)x)[i];
    __nv_bfloat16 h0 = __float2bfloat16(v.x);
    __nv_bfloat16 h1 = __float2bfloat16(v.y);
    __nv_bfloat16 h2 = __float2bfloat16(v.z);
    __nv_bfloat16 h3 = __float2bfloat16(v.w);
    __nv_bfloat16 l0 = __float2bfloat16(v.x - __bfloat162float(h0));
    __nv_bfloat16 l1 = __float2bfloat16(v.y - __bfloat162float(h1));
    __nv_bfloat16 l2 = __float2bfloat16(v.z - __bfloat162float(h2));
    __nv_bfloat16 l3 = __float2bfloat16(v.w - __bfloat162float(h3));
    __nv_bfloat162* xh2 = (__nv_bfloat162*)g_xh;
    __nv_bfloat162* xl2 = (__nv_bfloat162*)g_xl;
    xh2[2*i]   = __halves2bfloat162(h0, h1);
    xh2[2*i+1] = __halves2bfloat162(h2, h3);
    xl2[2*i]   = __halves2bfloat162(l0, l1);
    xl2[2*i+1] = __halves2bfloat162(l2, l3);
}

// prep_w: transpose W[D,H] -> [H,D] with bf16 hi/lo split
__global__ __launch_bounds__(256) void prep_w(const float* __restrict__ Wq,
                                              const float* __restrict__ Wk,
                                              const float* __restrict__ Wv)
{
    int idx = blockIdx.x * blockDim.x + threadIdx.x;
    if (idx >= 3 * H_ * D_) return;
    int t = idx / (H_ * D_);
    int r = idx % (H_ * D_);
    int n = r / D_;
    int k = r % D_;
    const float* W = (t == 0) ? Wq : (t == 1) ? Wk : Wv;
    float f = W[(size_t)k * H_ + n];
    __nv_bfloat16 h = __float2bfloat16(f);
    g_wh[idx] = h;
    g_wl[idx] = __float2bfloat16(f - __bfloat162float(h));
}

// ---------------------------------------------------------------------------
// proj_mma: cp.async double-buffered bf16x3 GEMM. 512 threads, 16 warps 4x4.
// ---------------------------------------------------------------------------
#define PPR 72
#define PARR (128 * PPR * 2)         // 18432 B per array
#define PST  (4 * PARR)              // stage = Ah, Al, Bh, Bl
#define PSMEM_BYTES (2 * PST)        // 147456 B

__global__ __launch_bounds__(512) void proj_mma()
{
    const uint32_t sb = smem_u32(dyn_sm);
    const int tid  = threadIdx.x;
    const int wid  = tid >> 5;
    const int lane = tid & 31;
    const int wm   = wid >> 2;
    const int wn   = wid & 3;
    const int mt0  = blockIdx.x;
    const int tgt  = blockIdx.y;

    const __nv_bfloat16* Ah = g_xh + (size_t)mt0 * 128 * D_;
    const __nv_bfloat16* Al = g_xl + (size_t)mt0 * 128 * D_;
    const __nv_bfloat16* Bh = g_wh + (size_t)tgt * H_ * D_;
    const __nv_bfloat16* Bl = g_wl + (size_t)tgt * H_ * D_;

    const uint32_t a_off = ((uint32_t)(lane & 15) * PPR + (lane >> 4) * 8) * 2;
    const uint32_t aoff0 = (uint32_t)(wm * 32) * PPR * 2 + a_off;
    const uint32_t boff0 = (uint32_t)(wn * 32) * PPR * 2 + a_off;

    float acc[2][4][4];
#pragma unroll
    for (int i = 0; i < 2; i++)
#pragma unroll
        for (int j = 0; j < 4; j++)
#pragma unroll
            for (int q = 0; q < 4; q++) acc[i][j][q] = 0.f;

    // Prologue: prefetch chunk 0 into stage 0.
    {
        const int kc = 0;
#pragma unroll
        for (int it = 0; it < 8; it++) {
            int idx = tid + it * 512;        // 0..4095
            int arr = idx >> 10;
            int rem = idx & 1023;
            int row = rem >> 3;
            int c16 = rem & 7;
            const __nv_bfloat16* src =
                (arr == 0) ? Ah : (arr == 1) ? Al : (arr == 2) ? Bh : Bl;
            uint32_t s = sb + arr * PARR + (row * PPR + c16 * 8) * 2;
            CP_ASYNC16(s, src + (size_t)row * D_ + kc + c16 * 8);
        }
        CP_COMMIT();
    }

    for (int c = 0; c < D_ / 64; c++) {
        const int st = c & 1;
        CP_WAIT0();
        __syncthreads();

        if (c + 1 < D_ / 64) {
            const int kc = (c + 1) * 64;
            const uint32_t stb = ((c + 1) & 1) * PST;
#pragma unroll
            for (int it = 0; it < 8; it++) {
                int idx = tid + it * 512;
                int arr = idx >> 10;
                int rem = idx & 1023;
                int row = rem >> 3;
                int c16 = rem & 7;
                const __nv_bfloat16* src =
                    (arr == 0) ? Ah : (arr == 1) ? Al : (arr == 2) ? Bh : Bl;
                uint32_t s = sb + stb + arr * PARR + (row * PPR + c16 * 8) * 2;
                CP_ASYNC16(s, src + (size_t)row * D_ + kc + c16 * 8);
            }
            CP_COMMIT();
        }

        const uint32_t uAh = sb + st * PST;
        const uint32_t uAl = uAh + PARR;
        const uint32_t uBh = uAh + 2 * PARR;
        const uint32_t uBl = uAh + 3 * PARR;

#pragma unroll
        for (int ks = 0; ks < 4; ks++) {
            const uint32_t kb = ks * 16 * 2;
            uint32_t ah[2][4], al[2][4], bh[4][2], bl[4][2];
            LDSM_X4(ah[0][0], ah[0][1], ah[0][2], ah[0][3], uAh + aoff0 + kb);
            LDSM_X4(ah[1][0], ah[1][1], ah[1][2], ah[1][3], uAh + aoff0 + 16 * PPR * 2 + kb);
            LDSM_X4(al[0][0], al[0][1], al[0][2], al[0][3], uAl + aoff0 + kb);
            LDSM_X4(al[1][0], al[1][1], al[1][2], al[1][3], uAl + aoff0 + 16 * PPR * 2 + kb);
            uint32_t t0, t1, t2, t3;
            LDSM_X4(t0, t1, t2, t3, uBh + boff0 + kb);
            bh[0][0] = t0; bh[0][1] = t2; bh[1][0] = t1; bh[1][1] = t3;
            LDSM_X4(t0, t1, t2, t3, uBh + boff0 + 16 * PPR * 2 + kb);
            bh[2][0] = t0; bh[2][1] = t2; bh[3][0] = t1; bh[3][1] = t3;
            LDSM_X4(t0, t1, t2, t3, uBl + boff0 + kb);
            bl[0][0] = t0; bl[0][1] = t2; bl[1][0] = t1; bl[1][1] = t3;
            LDSM_X4(t0, t1, t2, t3, uBl + boff0 + 16 * PPR * 2 + kb);
            bl[2][0] = t0; bl[2][1] = t2; bl[3][0] = t1; bl[3][1] = t3;

#pragma unroll
            for (int mi = 0; mi < 2; mi++)
#pragma unroll
                for (int ni = 0; ni < 4; ni++) {
                    MMA16816(acc[mi][ni], ah[mi], bh[ni]);
                    MMA16816(acc[mi][ni], al[mi], bh[ni]);
                    MMA16816(acc[mi][ni], ah[mi], bl[ni]);
                }
        }
    }

    __nv_bfloat16 *oh, *ol;
    if (tgt == 0)      { oh = g_qh; ol = g_ql; }
    else if (tgt == 1) { oh = g_kh; ol = g_kl; }
    else               { oh = g_vh; ol = g_vl; }
    const float scale = (tgt == 0) ? 0.08838834764831845f : 1.0f;

    const int r0 = mt0 * 128 + wm * 32 + (lane >> 2);
    const int c0 = wn * 32 + (lane & 3) * 2;
#pragma unroll
    for (int mi = 0; mi < 2; mi++)
#pragma unroll
        for (int ni = 0; ni < 4; ni++) {
            int cc = c0 + ni * 8;
#pragma unroll
            for (int hh = 0; hh < 2; hh++) {
                int rr = r0 + mi * 16 + hh * 8;
                float v0 = acc[mi][ni][2*hh + 0] * scale;
                float v1 = acc[mi][ni][2*hh + 1] * scale;
                __nv_bfloat16 h0 = __float2bfloat16(v0);
                __nv_bfloat16 h1 = __float2bfloat16(v1);
                __nv_bfloat16 l0 = __float2bfloat16(v0 - __bfloat162float(h0));
                __nv_bfloat16 l1 = __float2bfloat16(v1 - __bfloat162float(h1));
                *(__nv_bfloat162*)&oh[(size_t)rr * H_ + cc] = __halves2bfloat162(h0, h1);
                *(__nv_bfloat162*)&ol[(size_t)rr * H_ + cc] = __halves2bfloat162(l0, l1);
            }
        }
}

// ---------------------------------------------------------------------------
// attn_part: split-KV causal flash attention partial.
// Block i: qt = 31 - (i>>3); b = (i>>1)&3; half = i&1.
// half 0: k-tiles [0, qt+1); half 1: [qt+1, 2qt+2). Writes (O, m, l) partials.
// ---------------------------------------------------------------------------
#define QP 136
#define KP 136
#define QARR (128 * QP * 2)
#define KARR (64 * KP * 2)
#define OFF_QH 0
#define OFF_QL QARR
#define OFF_STG (2 * QARR)
#define STG_SZ (4 * KARR)
#define ATTN_SMEM (OFF_STG + 2 * STG_SZ)

__global__ __launch_bounds__(256, 1) void attn_part()
{
    char* smc = dyn_sm;
    const uint32_t sb = smem_u32(smc);
    const int tid  = threadIdx.x;
    const int w    = tid >> 5;
    const int lane = tid & 31;

    const int i    = blockIdx.x;
    const int qt   = 31 - (i >> 3);
    const int b    = (i >> 1) & 3;
    const int half = i & 1;
    const int q0   = qt * 128;
    const int kt0  = half ? (qt + 1) : 0;
    const int kt1  = half ? (2 * qt + 2) : (qt + 1);
    const size_t gbase = (size_t)b * T_ * H_;

    const uint32_t lrow  = (lane & 15);
    const uint32_t lcol8 = (lane >> 4) * 8;
    const int rA = (lane >> 2);
    const int cq = (lane & 3) * 2;

    // Load Q tile.
    {
        const size_t g0 = gbase + (size_t)q0 * H_;
#pragma unroll
        for (int it = 0; it < 8; it++) {
            int idx = tid + it * 256;
            int row = idx >> 4;
            int c8  = idx & 15;
            size_t g = g0 + (size_t)row * H_ + c8 * 8;
            int so = (row * QP + c8 * 8) * 2;
            *(uint4*)(smc + OFF_QH + so) = *(const uint4*)&g_qh[g];
            *(uint4*)(smc + OFF_QL + so) = *(const uint4*)&g_ql[g];
        }
    }

    // Prefetch first k-tile.
    {
        const int k0 = kt0 * 64;
        const int st = kt0 & 1;
#pragma unroll
        for (int it = 0; it < 16; it++) {
            int idx = tid + it * 256;
            int arr = idx >> 10;
            int row = (idx >> 4) & 63;
            int c8  = idx & 15;
            const __nv_bfloat16* src =
                (arr == 0) ? g_kh : (arr == 1) ? g_kl : (arr == 2) ? g_vh : g_vl;
            uint32_t s = sb + OFF_STG + st * STG_SZ + arr * KARR + (row * KP + c8 * 8) * 2;
            CP_ASYNC16(s, src + gbase + (size_t)(k0 + row) * H_ + c8 * 8);
        }
        CP_COMMIT();
    }

    float O[16][4];
#pragma unroll
    for (int n = 0; n < 16; n++)
#pragma unroll
        for (int q = 0; q < 4; q++) O[n][q] = 0.f;
    float mA = -1e30f, mB = -1e30f, lA = 0.f, lB = 0.f;

    for (int kt = kt0; kt < kt1; kt++) {
        const int st = kt & 1;
        const uint32_t stK = sb + OFF_STG + st * STG_SZ;
        CP_WAIT0();
        __syncthreads();

        if (kt + 1 < kt1) {
            const int k0n = (kt + 1) * 64;
            const int stn = (kt + 1) & 1;
#pragma unroll
            for (int it = 0; it < 16; it++) {
                int idx = tid + it * 256;
                int arr = idx >> 10;
                int row = (idx >> 4) & 63;
                int c8  = idx & 15;
                const __nv_bfloat16* src =
                    (arr == 0) ? g_kh : (arr == 1) ? g_kl : (arr == 2) ? g_vh : g_vl;
                uint32_t s = sb + OFF_STG + stn * STG_SZ + arr * KARR + (row * KP + c8 * 8) * 2;
                CP_ASYNC16(s, src + gbase + (size_t)(k0n + row) * H_ + c8 * 8);
            }
            CP_COMMIT();
        }

        const int k0 = kt * 64;

        // ---- S = Q K^T ----
        float accS[8][4];
#pragma unroll
        for (int n = 0; n < 8; n++)
#pragma unroll
            for (int q = 0; q < 4; q++) accS[n][q] = 0.f;

#pragma unroll
        for (int ks = 0; ks < 8; ks++) {
            uint32_t ah[4], al[4], bh[8][2], bl[8][2];
            uint32_t aQ = sb + OFF_QH + (((16 * w + lrow) * QP) + lcol8 + ks * 16) * 2;
            LDSM_X4(ah[0], ah[1], ah[2], ah[3], aQ);
            LDSM_X4(al[0], al[1], al[2], al[3], aQ + (OFF_QL - OFF_QH));
            uint32_t t0, t1, t2, t3;
#pragma unroll
            for (int nj = 0; nj < 4; nj++) {
                uint32_t aK = stK + (((nj * 16 + lrow) * KP) + lcol8 + ks * 16) * 2;
                LDSM_X4(t0, t1, t2, t3, aK);
                bh[2*nj][0] = t0; bh[2*nj][1] = t2;
                bh[2*nj+1][0] = t1; bh[2*nj+1][1] = t3;
                LDSM_X4(t0, t1, t2, t3, aK + KARR);
                bl[2*nj][0] = t0; bl[2*nj][1] = t2;
                bl[2*nj+1][0] = t1; bl[2*nj+1][1] = t3;
            }
#pragma unroll
            for (int n = 0; n < 8; n++) {
                MMA16816(accS[n], ah, bh[n]);
                MMA16816(accS[n], al, bh[n]);
                MMA16816(accS[n], ah, bl[n]);
            }
        }

        // ---- Causal mask ----
        if (k0 + 63 > q0 + 16 * w) {
            const int qgA = q0 + 16 * w + rA;
            const int qgB = qgA + 8;
#pragma unroll
            for (int n = 0; n < 8; n++) {
                int kg0 = k0 + n * 8 + cq;
                int kg1 = kg0 + 1;
                if (kg0 > qgA) accS[n][0] = -1e30f;
                if (kg1 > qgA) accS[n][1] = -1e30f;
                if (kg0 > qgB) accS[n][2] = -1e30f;
                if (kg1 > qgB) accS[n][3] = -1e30f;
            }
        }

        // ---- Online softmax in registers ----
        float mxA = -1e30f, mxB = -1e30f;
#pragma unroll
        for (int n = 0; n < 8; n++) {
            mxA = fmaxf(mxA, fmaxf(accS[n][0], accS[n][1]));
            mxB = fmaxf(mxB, fmaxf(accS[n][2], accS[n][3]));
        }
        mxA = fmaxf(mxA, __shfl_xor_sync(0xffffffffu, mxA, 1));
        mxA = fmaxf(mxA, __shfl_xor_sync(0xffffffffu, mxA, 2));
        mxB = fmaxf(mxB, __shfl_xor_sync(0xffffffffu, mxB, 1));
        mxB = fmaxf(mxB, __shfl_xor_sync(0xffffffffu, mxB, 2));

        float mAn = fmaxf(mA, mxA);
        float mBn = fmaxf(mB, mxB);
        float aAl = __expf(mA - mAn);
        float aBl = __expf(mB - mBn);
        mA = mAn; mB = mBn;

        float sA = 0.f, sB = 0.f;
#pragma unroll
        for (int n = 0; n < 8; n++) {
            accS[n][0] = __expf(accS[n][0] - mAn);
            accS[n][1] = __expf(accS[n][1] - mAn);
            accS[n][2] = __expf(accS[n][2] - mBn);
            accS[n][3] = __expf(accS[n][3] - mBn);
            sA += accS[n][0] + accS[n][1];
            sB += accS[n][2] + accS[n][3];
        }
        sA += __shfl_xor_sync(0xffffffffu, sA, 1);
        sA += __shfl_xor_sync(0xffffffffu, sA, 2);
        sB += __shfl_xor_sync(0xffffffffu, sB, 1);
        sB += __shfl_xor_sync(0xffffffffu, sB, 2);
        lA = lA * aAl + sA;
        lB = lB * aBl + sB;

#pragma unroll
        for (int n = 0; n < 16; n++) {
            O[n][0] *= aAl; O[n][1] *= aAl;
            O[n][2] *= aBl; O[n][3] *= aBl;
        }

        // ---- O += P V ----
        const uint32_t stV = stK + 2 * KARR;
#pragma unroll
        for (int ks = 0; ks < 4; ks++) {
            uint32_t ph[4], pl[4];
            {
                const int j0 = 2 * ks, j1 = 2 * ks + 1;
                float p00 = accS[j0][0], p01 = accS[j0][1];
                float p02 = accS[j0][2], p03 = accS[j0][3];
                float p10 = accS[j1][0], p11 = accS[j1][1];
                float p12 = accS[j1][2], p13 = accS[j1][3];
                ph[0] = pack_bf16(p00, p01);
                ph[1] = pack_bf16(p02, p03);
                ph[2] = pack_bf16(p10, p11);
                ph[3] = pack_bf16(p12, p13);
                __nv_bfloat162* h;
                h = (__nv_bfloat162*)&ph[0];
                pl[0] = pack_bf16(p00 - __bfloat162float(h->x), p01 - __bfloat162float(h->y));
                h = (__nv_bfloat162*)&ph[1];
                pl[1] = pack_bf16(p02 - __bfloat162float(h->x), p03 - __bfloat162float(h->y));
                h = (__nv_bfloat162*)&ph[2];
                pl[2] = pack_bf16(p10 - __bfloat162float(h->x), p11 - __bfloat162float(h->y));
                h = (__nv_bfloat162*)&ph[3];
                pl[3] = pack_bf16(p12 - __bfloat162float(h->x), p13 - __bfloat162float(h->y));
            }

            uint32_t vh[16][2], vl[16][2];
            uint32_t t0, t1, t2, t3;
#pragma unroll
            for (int nj = 0; nj < 8; nj++) {
                uint32_t aV = stV + (((ks * 16 + lrow) * KP) + nj * 16 + lcol8) * 2;
                LDSM_X4_T(t0, t1, t2, t3, aV);
                vh[2*nj][0] = t0; vh[2*nj][1] = t1;
                vh[2*nj+1][0] = t2; vh[2*nj+1][1] = t3;
                LDSM_X4_T(t0, t1, t2, t3, aV + KARR);
                vl[2*nj][0] = t0; vl[2*nj][1] = t1;
                vl[2*nj+1][0] = t2; vl[2*nj+1][1] = t3;
            }
#pragma unroll
            for (int n = 0; n < 16; n++) {
                MMA16816(O[n], ph, vh[n]);
                MMA16816(O[n], pl, vh[n]);
                MMA16816(O[n], ph, vl[n]);
            }
        }
    }

    // ---- Write unnormalized partial O, plus m/l. ----
    float* po = g_po + (size_t)half * M_TOT * H_;
    const int rowA = q0 + 16 * w + rA;
    const size_t grA = (size_t)b * T_ + rowA;
#pragma unroll
    for (int n = 0; n < 16; n++) {
        int col = n * 8 + cq;
        *(float2*)&po[grA * H_ + col]       = make_float2(O[n][0], O[n][1]);
        *(float2*)&po[(grA + 8) * H_ + col] = make_float2(O[n][2], O[n][3]);
    }
    if ((lane & 3) == 0) {
        g_pm[(size_t)half * M_TOT + grA]     = mA;
        g_pm[(size_t)half * M_TOT + grA + 8] = mB;
        g_pl[(size_t)half * M_TOT + grA]     = lA;
        g_pl[(size_t)half * M_TOT + grA + 8] = lB;
    }
}

// ---------------------------------------------------------------------------
// attn_merge: combine two partials.
// ---------------------------------------------------------------------------
__global__ __launch_bounds__(256) void attn_merge(float* __restrict__ out)
{
    size_t idx = (size_t)blockIdx.x * 256 + threadIdx.x;   // over M_TOT*32
    size_t row = idx >> 5;
    int c4 = (int)(idx & 31) * 4;
    float mA = g_pm[row], mB = g_pm[M_TOT + row];
    float lA = g_pl[row], lB = g_pl[M_TOT + row];
    float m = fmaxf(mA, mB);
    float wA = __expf(mA - m), wB = __expf(mB - m);
    float inv = 1.f / (wA * lA + wB * lB);
    float4 a = *(float4*)&g_po[row * H_ + c4];
    float4 c = *(float4*)&g_po[(size_t)M_TOT * H_ + row * H_ + c4];
    float4 o;
    o.x = (wA * a.x + wB * c.x) * inv;
    o.y = (wA * a.y + wB * c.y) * inv;
    o.z = (wA * a.z + wB * c.z) * inv;
    o.w = (wA * a.w + wB * c.w) * inv;
    *(float4*)&out[row * H_ + c4] = o;
}

// ---------------------------------------------------------------------------
extern "C" void kernel_launch(void* const* d_in, const int* in_sizes, int n_in,
                              void* d_out, int out_size)
{
    const float* x  = (const float*)d_in[0];
    const float* Wq = (const float*)d_in[1];
    const float* Wk = (const float*)d_in[2];
    const float* Wv = (const float*)d_in[3];
    float* out = (float*)d_out;

    prep_x<<<(M_TOT * D_ / 4 + 255) / 256, 256>>>(x);
    prep_w<<<(3 * H_ * D_ + 255) / 256, 256>>>(Wq, Wk, Wv);

    cudaFuncSetAttribute(proj_mma, cudaFuncAttributeMaxDynamicSharedMemorySize,
                         PSMEM_BYTES);
    proj_mma<<<dim3(M_TOT / 128, 3), 512, PSMEM_BYTES>>>();

    cudaFuncSetAttribute(attn_part, cudaFuncAttributeMaxDynamicSharedMemorySize,
                         ATTN_SMEM);
    attn_part<<<256, 256, ATTN_SMEM>>>();

    attn_merge<<<M_TOT * 32 / 256, 256>>>(out);
}